// round 1
// baseline (speedup 1.0000x reference)
#include <cuda_runtime.h>
#include <cstddef>

// Problem shape (fixed for this dataset entry)
#define B_   16
#define QT_  2048
#define KT_  2048
#define D_   1024
#define MASKV (-4294967295.0f)   // -2^32 + 1, exactly representable in fp32

// 256 MB scratch for the masked logits / softmax probabilities.
// __device__ global is the sanctioned scratch mechanism (no cudaMalloc allowed).
__device__ float g_S[(size_t)B_ * QT_ * KT_];

// ---------------------------------------------------------------------------
// Packed fp32x2 FMA (Blackwell dual-rate fp32). ptxas will not auto-fuse from
// C++; must come from PTX fma.rn.f32x2 on 64-bit register pairs.
// ---------------------------------------------------------------------------
union F2 {
    float2 f;
    unsigned long long u;
};

__device__ __forceinline__ void fma2(F2& c, const F2& a, const F2& b) {
    asm("fma.rn.f32x2 %0, %1, %2, %0;" : "+l"(c.u) : "l"(a.u), "l"(b.u));
}

// ---------------------------------------------------------------------------
// 128x128x8 SGEMM, 256 threads, 8x8 register tile per thread, double-buffered
// SMEM. Computes C = A @ op(B) per batch (blockIdx.z).
//   B_IS_NK = true : B stored [N, Kd] row-major (use B^T)  -> GEMM1 (Q @ K^T)
//   B_IS_NK = false: B stored [Kd, N] row-major            -> GEMM2 (P @ V)
//   MASK_EPI: apply length mask in epilogue (GEMM1 only).
// All dims are multiples of the tile sizes for this problem -> no bounds checks.
// ---------------------------------------------------------------------------
template <bool B_IS_NK, bool MASK_EPI>
__global__ __launch_bounds__(256, 2)
void sgemm128(const float* __restrict__ A, const float* __restrict__ Bm,
              float* __restrict__ C, int N, int Kd,
              long strideA, long strideB, long strideC,
              const int* __restrict__ Qlen, const int* __restrict__ Klen)
{
    const int b = blockIdx.z;
    A  += (size_t)b * strideA;
    Bm += (size_t)b * strideB;
    C  += (size_t)b * strideC;

    __shared__ __align__(16) float As[2][8][128];
    __shared__ __align__(16) float Bs[2][8][128];

    const int tid = threadIdx.x;
    const int tx  = tid & 15;        // 0..15 -> 8 output columns each
    const int ty  = tid >> 4;        // 0..15 -> 8 output rows each
    const int m0  = blockIdx.y * 128;
    const int n0  = blockIdx.x * 128;

    // --- global->smem load mappings ---
    // A tile: rows m0..m0+127, k chunk of 8. One float4 per thread.
    const int ar_row = tid >> 1;          // 0..127
    const int ar_k   = (tid & 1) * 4;     // 0 or 4
    const float* Aptr = A + (size_t)(m0 + ar_row) * Kd + ar_k;

    const float* Bptr;
    int br_row = 0, br_k = 0, bc_k = 0, bc_col = 0;
    if (B_IS_NK) {
        br_row = tid >> 1;
        br_k   = (tid & 1) * 4;
        Bptr = Bm + (size_t)(n0 + br_row) * Kd + br_k;
    } else {
        bc_k   = tid >> 5;                // 0..7
        bc_col = (tid & 31) * 4;          // 0..124
        Bptr = Bm + (size_t)bc_k * N + n0 + bc_col;
    }

    // --- preload first tile ---
    {
        float4 va = *(const float4*)Aptr;
        As[0][ar_k + 0][ar_row] = va.x;
        As[0][ar_k + 1][ar_row] = va.y;
        As[0][ar_k + 2][ar_row] = va.z;
        As[0][ar_k + 3][ar_row] = va.w;
        float4 vb = *(const float4*)Bptr;
        if (B_IS_NK) {
            Bs[0][br_k + 0][br_row] = vb.x;
            Bs[0][br_k + 1][br_row] = vb.y;
            Bs[0][br_k + 2][br_row] = vb.z;
            Bs[0][br_k + 3][br_row] = vb.w;
        } else {
            *(float4*)&Bs[0][bc_k][bc_col] = vb;
        }
    }
    __syncthreads();

    F2 c[8][4];
    #pragma unroll
    for (int i = 0; i < 8; i++)
        #pragma unroll
        for (int j = 0; j < 4; j++) c[i][j].u = 0ull;

    const int ntiles = Kd / 8;
    int buf = 0;

    for (int t = 0; t < ntiles; ++t) {
        float4 na, nb;
        const bool has_next = (t + 1 < ntiles);
        if (has_next) {
            Aptr += 8;
            if (B_IS_NK) Bptr += 8;
            else         Bptr += (size_t)8 * N;
            na = *(const float4*)Aptr;
            nb = *(const float4*)Bptr;
        }

        #pragma unroll
        for (int k = 0; k < 8; ++k) {
            float ar[8];
            *(float4*)&ar[0] = *(const float4*)&As[buf][k][ty * 8];
            *(float4*)&ar[4] = *(const float4*)&As[buf][k][ty * 8 + 4];
            F2 bp[4];
            const float2* bsrc = (const float2*)&Bs[buf][k][tx * 8];
            bp[0].f = bsrc[0]; bp[1].f = bsrc[1];
            bp[2].f = bsrc[2]; bp[3].f = bsrc[3];
            #pragma unroll
            for (int i = 0; i < 8; ++i) {
                F2 ap;
                ap.f.x = ar[i];
                ap.f.y = ar[i];
                fma2(c[i][0], ap, bp[0]);
                fma2(c[i][1], ap, bp[1]);
                fma2(c[i][2], ap, bp[2]);
                fma2(c[i][3], ap, bp[3]);
            }
        }

        if (has_next) {
            const int nbuf = buf ^ 1;
            As[nbuf][ar_k + 0][ar_row] = na.x;
            As[nbuf][ar_k + 1][ar_row] = na.y;
            As[nbuf][ar_k + 2][ar_row] = na.z;
            As[nbuf][ar_k + 3][ar_row] = na.w;
            if (B_IS_NK) {
                Bs[nbuf][br_k + 0][br_row] = nb.x;
                Bs[nbuf][br_k + 1][br_row] = nb.y;
                Bs[nbuf][br_k + 2][br_row] = nb.z;
                Bs[nbuf][br_k + 3][br_row] = nb.w;
            } else {
                *(float4*)&Bs[nbuf][bc_k][bc_col] = nb;
            }
        }
        __syncthreads();
        buf ^= 1;
    }

    // --- epilogue ---
    int ql = 0, kl = 0;
    if (MASK_EPI) { ql = Qlen[b]; kl = Klen[b]; }

    #pragma unroll
    for (int i = 0; i < 8; ++i) {
        const int m = m0 + ty * 8 + i;
        float* crow = C + (size_t)m * N + n0 + tx * 8;
        if (MASK_EPI) {
            const bool qv = (m < ql);
            #pragma unroll
            for (int j = 0; j < 4; ++j) {
                const int n = n0 + tx * 8 + 2 * j;
                float2 v = c[i][j].f;
                v.x = (qv && (n     < kl)) ? v.x : MASKV;
                v.y = (qv && (n + 1 < kl)) ? v.y : MASKV;
                ((float2*)crow)[j] = v;
            }
        } else {
            #pragma unroll
            for (int j = 0; j < 4; ++j) {
                ((float2*)crow)[j] = c[i][j].f;
            }
        }
    }
}

// ---------------------------------------------------------------------------
// Row softmax over KT=2048, in place. One block (256 threads) per row.
// All-masked rows (invalid q) naturally become uniform 1/KT, matching the
// reference (output = mean of V). Masked columns under a valid max underflow
// exp() to exactly 0.
// ---------------------------------------------------------------------------
__global__ __launch_bounds__(256)
void softmax_rows(float* __restrict__ S)
{
    float* row = S + (size_t)blockIdx.x * KT_;
    const int tid  = threadIdx.x;
    const int lane = tid & 31;
    const int wid  = tid >> 5;
    __shared__ float redmax[8];
    __shared__ float redsum[8];

    float4 v0 = ((const float4*)row)[tid];
    float4 v1 = ((const float4*)row)[tid + 256];

    float mx = fmaxf(fmaxf(fmaxf(v0.x, v0.y), fmaxf(v0.z, v0.w)),
                     fmaxf(fmaxf(v1.x, v1.y), fmaxf(v1.z, v1.w)));
    #pragma unroll
    for (int o = 16; o; o >>= 1) mx = fmaxf(mx, __shfl_xor_sync(0xffffffffu, mx, o));
    if (lane == 0) redmax[wid] = mx;
    __syncthreads();
    mx = redmax[0];
    #pragma unroll
    for (int i = 1; i < 8; ++i) mx = fmaxf(mx, redmax[i]);

    v0.x = expf(v0.x - mx); v0.y = expf(v0.y - mx);
    v0.z = expf(v0.z - mx); v0.w = expf(v0.w - mx);
    v1.x = expf(v1.x - mx); v1.y = expf(v1.y - mx);
    v1.z = expf(v1.z - mx); v1.w = expf(v1.w - mx);

    float s = ((v0.x + v0.y) + (v0.z + v0.w)) + ((v1.x + v1.y) + (v1.z + v1.w));
    #pragma unroll
    for (int o = 16; o; o >>= 1) s += __shfl_xor_sync(0xffffffffu, s, o);
    if (lane == 0) redsum[wid] = s;
    __syncthreads();
    s = redsum[0];
    #pragma unroll
    for (int i = 1; i < 8; ++i) s += redsum[i];

    const float inv = 1.0f / s;
    v0.x *= inv; v0.y *= inv; v0.z *= inv; v0.w *= inv;
    v1.x *= inv; v1.y *= inv; v1.z *= inv; v1.w *= inv;

    ((float4*)row)[tid]       = v0;
    ((float4*)row)[tid + 256] = v1;
}

// ---------------------------------------------------------------------------
// Launch: GEMM1 (masked logits) -> softmax -> GEMM2. Graph-capturable:
// kernel launches only, no allocation, no sync.
// Input order per metadata: Q, K, V, Q_lengths, K_lengths.
// ---------------------------------------------------------------------------
extern "C" void kernel_launch(void* const* d_in, const int* in_sizes, int n_in,
                              void* d_out, int out_size)
{
    const float* Q    = (const float*)d_in[0];
    const float* K    = (const float*)d_in[1];
    const float* V    = (const float*)d_in[2];
    const int*   Qlen = (const int*)d_in[3];
    const int*   Klen = (const int*)d_in[4];
    float*       O    = (float*)d_out;

    float* S = nullptr;
    cudaGetSymbolAddress((void**)&S, g_S);

    // GEMM1: S[b, q, k] = sum_d Q[b,q,d] * K[b,k,d]  (+ mask epilogue)
    sgemm128<true, true><<<dim3(KT_ / 128, QT_ / 128, B_), 256>>>(
        Q, K, S, /*N=*/KT_, /*Kd=*/D_,
        (long)QT_ * D_, (long)KT_ * D_, (long)QT_ * KT_, Qlen, Klen);

    // Row softmax in place.
    softmax_rows<<<B_ * QT_, 256>>>(S);

    // GEMM2: O[b, q, d] = sum_k P[b,q,k] * V[b,k,d]
    sgemm128<false, false><<<dim3(D_ / 128, QT_ / 128, B_), 256>>>(
        S, V, O, /*N=*/D_, /*Kd=*/KT_,
        (long)QT_ * KT_, (long)KT_ * D_, (long)QT_ * D_, nullptr, nullptr);
}

// round 3
// speedup vs baseline: 2.5813x; 2.5813x over previous
#include <cuda_runtime.h>
#include <cuda_bf16.h>
#include <cstdint>
#include <cstddef>

#define B_   16
#define QT_  2048
#define KT_  2048
#define D_   1024
#define MASKV (-4294967295.0f)   // -2^32 + 1

// ---------------------------------------------------------------------------
// Scratch (device globals — the sanctioned no-cudaMalloc mechanism), ~0.96 GB
// ---------------------------------------------------------------------------
__device__ float         g_S [(size_t)B_ * QT_ * KT_];    // 256 MB logits
__device__ __nv_bfloat16 g_Qh[(size_t)B_ * QT_ * D_];
__device__ __nv_bfloat16 g_Ql[(size_t)B_ * QT_ * D_];
__device__ __nv_bfloat16 g_Kh[(size_t)B_ * KT_ * D_];
__device__ __nv_bfloat16 g_Kl[(size_t)B_ * KT_ * D_];
__device__ __nv_bfloat16 g_Ph[(size_t)B_ * QT_ * KT_];
__device__ __nv_bfloat16 g_Pl[(size_t)B_ * QT_ * KT_];
__device__ __nv_bfloat16 g_Vh[(size_t)B_ * D_ * KT_];     // V^T hi  [d][k]
__device__ __nv_bfloat16 g_Vl[(size_t)B_ * D_ * KT_];     // V^T lo

// ---------------------------------------------------------------------------
// Helpers (baseline sm_80+ features only: cp.async, ldmatrix, mma.sync)
// ---------------------------------------------------------------------------
__device__ __forceinline__ uint32_t smem_u32(const void* p) {
    uint32_t a;
    asm("{ .reg .u64 t; cvta.to.shared.u64 t, %1; cvt.u32.u64 %0, t; }"
        : "=r"(a) : "l"(p));
    return a;
}
__device__ __forceinline__ void cpa16(uint32_t dst, const void* src) {
    asm volatile("cp.async.cg.shared.global [%0], [%1], 16;" :: "r"(dst), "l"(src));
}
#define CP_COMMIT() asm volatile("cp.async.commit_group;" ::: "memory")
#define CP_WAIT0()  asm volatile("cp.async.wait_group 0;" ::: "memory")

__device__ __forceinline__ void lm4(uint32_t* r, uint32_t addr) {
    asm volatile("ldmatrix.sync.aligned.m8n8.x4.shared.b16 {%0,%1,%2,%3}, [%4];"
                 : "=r"(r[0]), "=r"(r[1]), "=r"(r[2]), "=r"(r[3]) : "r"(addr));
}
__device__ __forceinline__ void mma16816(float* c, const uint32_t* a,
                                         uint32_t b0, uint32_t b1) {
    asm volatile(
        "mma.sync.aligned.m16n8k16.row.col.f32.bf16.bf16.f32 "
        "{%0,%1,%2,%3}, {%4,%5,%6,%7}, {%8,%9}, {%0,%1,%2,%3};"
        : "+f"(c[0]), "+f"(c[1]), "+f"(c[2]), "+f"(c[3])
        : "r"(a[0]), "r"(a[1]), "r"(a[2]), "r"(a[3]), "r"(b0), "r"(b1));
}

// ---------------------------------------------------------------------------
// bf16 split GEMM: C[M,N] = (Ah+Al) @ (Bh+Bl)^T, dropping Al@Bl.
// A parts: [M, Kfull] K-major. B parts: [N, Kfull] K-major.
// Block 128x128, 8 warps (64x32 warp tiles), BK=32, double-buffered cp.async.
// Smem tiles padded to 40 bf16 per 32-elem row (conflict-free ldmatrix).
// ---------------------------------------------------------------------------
#define PS   40                   // padded row stride in bf16 elements
#define PART_BYTES (128 * PS * 2) // 10240 B per 128x32 part-tile
#define BUF_BYTES  (4 * PART_BYTES)

template <bool MASK>
__global__ __launch_bounds__(256, 2)
void mma_gemm(const __nv_bfloat16* __restrict__ A0, const __nv_bfloat16* __restrict__ A1,
              const __nv_bfloat16* __restrict__ B0, const __nv_bfloat16* __restrict__ B1,
              float* __restrict__ C, int Kfull, int ldc,
              long strideA, long strideB, long strideC,
              const int* __restrict__ Qlen, const int* __restrict__ Klen)
{
    extern __shared__ char smem[];
    const uint32_t sb = smem_u32(smem);

    const int tid  = threadIdx.x;
    const int wid  = tid >> 5;
    const int lane = tid & 31;
    const int wm   = wid >> 2;          // 0..1  (64-row slab)
    const int wn   = wid & 3;           // 0..3  (32-col slab)
    const int bz   = blockIdx.z;
    const int n0   = blockIdx.x * 128;
    const int m0   = blockIdx.y * 128;

    const __nv_bfloat16* Ap[2] = { A0 + (size_t)bz * strideA, A1 + (size_t)bz * strideA };
    const __nv_bfloat16* Bp[2] = { B0 + (size_t)bz * strideB, B1 + (size_t)bz * strideB };

    // cp.async mapping: 512 16B-chunks per part, 2 per thread
    const int ld_row0 = tid >> 2;            // rows tid/4 and tid/4+64
    const int ld_c    = (tid & 3) * 8;       // bf16 col within 32 (chunks of 8)

    auto load_chunk = [&](int k0, int buf) {
        const uint32_t tb = sb + (uint32_t)buf * BUF_BYTES;
        #pragma unroll
        for (int p = 0; p < 2; ++p) {
            #pragma unroll
            for (int j = 0; j < 2; ++j) {
                const int r = ld_row0 + 64 * j;
                const uint32_t so = (uint32_t)(r * PS + ld_c) * 2;
                cpa16(tb + p * PART_BYTES + so,
                      Ap[p] + (size_t)(m0 + r) * Kfull + k0 + ld_c);
                cpa16(tb + (2 + p) * PART_BYTES + so,
                      Bp[p] + (size_t)(n0 + r) * Kfull + k0 + ld_c);
            }
        }
    };

    float acc[4][4][4];
    #pragma unroll
    for (int i = 0; i < 4; ++i)
        #pragma unroll
        for (int j = 0; j < 4; ++j)
            #pragma unroll
            for (int q = 0; q < 4; ++q) acc[i][j][q] = 0.f;

    load_chunk(0, 0);
    CP_COMMIT();

    // ldmatrix lane addressing (bf16 elem offsets, *2 for bytes)
    const int a_row = (lane & 15);            // + mt*16 + wm*64
    const int a_col = (lane >> 4) * 8;        // + kk*16
    const int b_row = (lane & 7) + ((lane >> 4) << 3);   // + np*16 + wn*32
    const int b_col = (((lane >> 3) & 1) << 3);          // + kk*16

    const int nchunks = Kfull / 32;
    for (int t = 0; t < nchunks; ++t) {
        const int buf = t & 1;
        CP_WAIT0();
        __syncthreads();
        if (t + 1 < nchunks) {
            load_chunk((t + 1) * 32, buf ^ 1);
            CP_COMMIT();
        }

        const uint32_t tb  = sb + (uint32_t)buf * BUF_BYTES;
        const uint32_t Ah_ = tb;
        const uint32_t Al_ = tb + PART_BYTES;
        const uint32_t Bh_ = tb + 2 * PART_BYTES;
        const uint32_t Bl_ = tb + 3 * PART_BYTES;

        #pragma unroll
        for (int kk = 0; kk < 2; ++kk) {
            uint32_t bh[2][4], bl[2][4], a[4][4];
            #pragma unroll
            for (int np = 0; np < 2; ++np) {
                const uint32_t boff =
                    (uint32_t)((wn * 32 + np * 16 + b_row) * PS + kk * 16 + b_col) * 2;
                lm4(bh[np], Bh_ + boff);
                lm4(bl[np], Bl_ + boff);
            }
            #pragma unroll
            for (int mt = 0; mt < 4; ++mt)
                lm4(a[mt], Ah_ + (uint32_t)((wm * 64 + mt * 16 + a_row) * PS
                                            + kk * 16 + a_col) * 2);
            // hh + hl
            #pragma unroll
            for (int mt = 0; mt < 4; ++mt)
                #pragma unroll
                for (int nf = 0; nf < 4; ++nf) {
                    mma16816(acc[mt][nf], a[mt], bh[nf >> 1][(nf & 1) * 2],
                                                 bh[nf >> 1][(nf & 1) * 2 + 1]);
                    mma16816(acc[mt][nf], a[mt], bl[nf >> 1][(nf & 1) * 2],
                                                 bl[nf >> 1][(nf & 1) * 2 + 1]);
                }
            // lh
            #pragma unroll
            for (int mt = 0; mt < 4; ++mt)
                lm4(a[mt], Al_ + (uint32_t)((wm * 64 + mt * 16 + a_row) * PS
                                            + kk * 16 + a_col) * 2);
            #pragma unroll
            for (int mt = 0; mt < 4; ++mt)
                #pragma unroll
                for (int nf = 0; nf < 4; ++nf)
                    mma16816(acc[mt][nf], a[mt], bh[nf >> 1][(nf & 1) * 2],
                                                 bh[nf >> 1][(nf & 1) * 2 + 1]);
        }
        __syncthreads();
    }

    // --- epilogue ---
    int ql = 0, kl = 0;
    if (MASK) { ql = Qlen[bz]; kl = Klen[bz]; }
    float* Cb = C + (size_t)bz * strideC;

    #pragma unroll
    for (int mt = 0; mt < 4; ++mt) {
        #pragma unroll
        for (int nf = 0; nf < 4; ++nf) {
            const int n = n0 + wn * 32 + nf * 8 + (lane & 3) * 2;
            #pragma unroll
            for (int h = 0; h < 2; ++h) {
                const int m = m0 + wm * 64 + mt * 16 + (lane >> 2) + h * 8;
                float2 v = make_float2(acc[mt][nf][h * 2], acc[mt][nf][h * 2 + 1]);
                if (MASK) {
                    const bool qv = (m < ql);
                    v.x = (qv && (n     < kl)) ? v.x : MASKV;
                    v.y = (qv && (n + 1 < kl)) ? v.y : MASKV;
                }
                *(float2*)(Cb + (size_t)m * ldc + n) = v;
            }
        }
    }
}

// ---------------------------------------------------------------------------
// 2-way bf16 split (elementwise), 4 floats per thread
// ---------------------------------------------------------------------------
__global__ __launch_bounds__(256)
void split2_k(const float* __restrict__ x, __nv_bfloat16* __restrict__ h,
              __nv_bfloat16* __restrict__ l)
{
    const size_t i = (size_t)blockIdx.x * blockDim.x + threadIdx.x;
    float4 v = ((const float4*)x)[i];
    float vv[4] = {v.x, v.y, v.z, v.w};
    __nv_bfloat16 hh[4], ll[4];
    #pragma unroll
    for (int j = 0; j < 4; ++j) {
        hh[j] = __float2bfloat16_rn(vv[j]);
        ll[j] = __float2bfloat16_rn(vv[j] - __bfloat162float(hh[j]));
    }
    ((__nv_bfloat162*)h)[2 * i + 0] = __nv_bfloat162(hh[0], hh[1]);
    ((__nv_bfloat162*)h)[2 * i + 1] = __nv_bfloat162(hh[2], hh[3]);
    ((__nv_bfloat162*)l)[2 * i + 0] = __nv_bfloat162(ll[0], ll[1]);
    ((__nv_bfloat162*)l)[2 * i + 1] = __nv_bfloat162(ll[2], ll[3]);
}

// ---------------------------------------------------------------------------
// V transpose + 2-way split: V[b][k][d] -> Vt{h,l}[b][d][k]
// ---------------------------------------------------------------------------
__global__ __launch_bounds__(256)
void vt_split2(const float* __restrict__ V, __nv_bfloat16* __restrict__ Th,
               __nv_bfloat16* __restrict__ Tl)
{
    __shared__ float tile[32][33];
    const int bz = blockIdx.z;
    const int d0 = blockIdx.x * 32;
    const int k0 = blockIdx.y * 32;
    const int tx = threadIdx.x, ty = threadIdx.y;   // 32 x 8
    const float* src = V + (size_t)bz * KT_ * D_;
    #pragma unroll
    for (int j = 0; j < 4; ++j)
        tile[ty + 8 * j][tx] = src[(size_t)(k0 + ty + 8 * j) * D_ + d0 + tx];
    __syncthreads();
    __nv_bfloat16* th = Th + (size_t)bz * D_ * KT_;
    __nv_bfloat16* tl = Tl + (size_t)bz * D_ * KT_;
    #pragma unroll
    for (int j = 0; j < 4; ++j) {
        const int d = d0 + ty + 8 * j;
        const float f = tile[tx][ty + 8 * j];
        const __nv_bfloat16 h = __float2bfloat16_rn(f);
        const __nv_bfloat16 l = __float2bfloat16_rn(f - __bfloat162float(h));
        th[(size_t)d * KT_ + k0 + tx] = h;
        tl[(size_t)d * KT_ + k0 + tx] = l;
    }
}

// ---------------------------------------------------------------------------
// Row softmax over KT=2048 + 2-way bf16 split of probabilities
// ---------------------------------------------------------------------------
__global__ __launch_bounds__(256)
void softmax_split(const float* __restrict__ S, __nv_bfloat16* __restrict__ Ph,
                   __nv_bfloat16* __restrict__ Pl)
{
    const size_t row = blockIdx.x;
    const float* srow = S + row * KT_;
    const int tid = threadIdx.x, lane = tid & 31, wid = tid >> 5;
    __shared__ float red[8];

    float4 v0 = ((const float4*)srow)[tid];
    float4 v1 = ((const float4*)srow)[tid + 256];

    float mx = fmaxf(fmaxf(fmaxf(v0.x, v0.y), fmaxf(v0.z, v0.w)),
                     fmaxf(fmaxf(v1.x, v1.y), fmaxf(v1.z, v1.w)));
    #pragma unroll
    for (int o = 16; o; o >>= 1) mx = fmaxf(mx, __shfl_xor_sync(~0u, mx, o));
    if (lane == 0) red[wid] = mx;
    __syncthreads();
    mx = red[0];
    #pragma unroll
    for (int i = 1; i < 8; ++i) mx = fmaxf(mx, red[i]);
    __syncthreads();

    v0.x = expf(v0.x - mx); v0.y = expf(v0.y - mx);
    v0.z = expf(v0.z - mx); v0.w = expf(v0.w - mx);
    v1.x = expf(v1.x - mx); v1.y = expf(v1.y - mx);
    v1.z = expf(v1.z - mx); v1.w = expf(v1.w - mx);

    float s = ((v0.x + v0.y) + (v0.z + v0.w)) + ((v1.x + v1.y) + (v1.z + v1.w));
    #pragma unroll
    for (int o = 16; o; o >>= 1) s += __shfl_xor_sync(~0u, s, o);
    if (lane == 0) red[wid] = s;
    __syncthreads();
    s = red[0];
    #pragma unroll
    for (int i = 1; i < 8; ++i) s += red[i];

    const float inv = 1.0f / s;
    float p[8] = {v0.x * inv, v0.y * inv, v0.z * inv, v0.w * inv,
                  v1.x * inv, v1.y * inv, v1.z * inv, v1.w * inv};
    __nv_bfloat16 hh[8], ll[8];
    #pragma unroll
    for (int j = 0; j < 8; ++j) {
        hh[j] = __float2bfloat16_rn(p[j]);
        ll[j] = __float2bfloat16_rn(p[j] - __bfloat162float(hh[j]));
    }
    __nv_bfloat162* ph = (__nv_bfloat162*)(Ph + row * KT_);
    __nv_bfloat162* pl = (__nv_bfloat162*)(Pl + row * KT_);
    ph[tid * 2 + 0]         = __nv_bfloat162(hh[0], hh[1]);
    ph[tid * 2 + 1]         = __nv_bfloat162(hh[2], hh[3]);
    ph[(256 + tid) * 2 + 0] = __nv_bfloat162(hh[4], hh[5]);
    ph[(256 + tid) * 2 + 1] = __nv_bfloat162(hh[6], hh[7]);
    pl[tid * 2 + 0]         = __nv_bfloat162(ll[0], ll[1]);
    pl[tid * 2 + 1]         = __nv_bfloat162(ll[2], ll[3]);
    pl[(256 + tid) * 2 + 0] = __nv_bfloat162(ll[4], ll[5]);
    pl[(256 + tid) * 2 + 1] = __nv_bfloat162(ll[6], ll[7]);
}

// ---------------------------------------------------------------------------
// Launch pipeline (graph-capturable: launches only)
// ---------------------------------------------------------------------------
extern "C" void kernel_launch(void* const* d_in, const int* in_sizes, int n_in,
                              void* d_out, int out_size)
{
    const float* Q    = (const float*)d_in[0];
    const float* K    = (const float*)d_in[1];
    const float* V    = (const float*)d_in[2];
    const int*   Qlen = (const int*)d_in[3];
    const int*   Klen = (const int*)d_in[4];
    float*       O    = (float*)d_out;

    float* S; __nv_bfloat16 *Qh, *Ql, *Kh, *Kl, *Ph, *Pl, *Vh, *Vl;
    cudaGetSymbolAddress((void**)&S,  g_S);
    cudaGetSymbolAddress((void**)&Qh, g_Qh); cudaGetSymbolAddress((void**)&Ql, g_Ql);
    cudaGetSymbolAddress((void**)&Kh, g_Kh); cudaGetSymbolAddress((void**)&Kl, g_Kl);
    cudaGetSymbolAddress((void**)&Ph, g_Ph); cudaGetSymbolAddress((void**)&Pl, g_Pl);
    cudaGetSymbolAddress((void**)&Vh, g_Vh); cudaGetSymbolAddress((void**)&Vl, g_Vl);

    const int SMEM = 2 * BUF_BYTES;   // 81920
    cudaFuncSetAttribute(mma_gemm<true>,  cudaFuncAttributeMaxDynamicSharedMemorySize, SMEM);
    cudaFuncSetAttribute(mma_gemm<false>, cudaFuncAttributeMaxDynamicSharedMemorySize, SMEM);

    // 1. split Q, K into 2-way bf16
    const int nQ4 = (B_ * QT_ * D_) / 4;
    split2_k<<<nQ4 / 256, 256>>>(Q, Qh, Ql);
    split2_k<<<nQ4 / 256, 256>>>(K, Kh, Kl);

    // 2. transpose + split V
    vt_split2<<<dim3(D_ / 32, KT_ / 32, B_), dim3(32, 8)>>>(V, Vh, Vl);

    // 3. GEMM1: S = Q K^T (+ mask epilogue)
    mma_gemm<true><<<dim3(KT_ / 128, QT_ / 128, B_), 256, SMEM>>>(
        Qh, Ql, Kh, Kl, S, /*Kfull=*/D_, /*ldc=*/KT_,
        (long)QT_ * D_, (long)KT_ * D_, (long)QT_ * KT_, Qlen, Klen);

    // 4. softmax + split P
    softmax_split<<<B_ * QT_, 256>>>(S, Ph, Pl);

    // 5. GEMM2: O = P V   (B = V^T, K-major)
    mma_gemm<false><<<dim3(D_ / 128, QT_ / 128, B_), 256, SMEM>>>(
        Ph, Pl, Vh, Vl, O, /*Kfull=*/KT_, /*ldc=*/D_,
        (long)QT_ * KT_, (long)D_ * KT_, (long)QT_ * D_, nullptr, nullptr);
}

// round 4
// speedup vs baseline: 6.2368x; 2.4162x over previous
#include <cuda_runtime.h>
#include <cuda_bf16.h>
#include <cstdint>
#include <cstddef>

#define B_   16
#define QT_  2048
#define KT_  2048
#define D_   1024

// ---------------------------------------------------------------------------
// Scratch (device globals), ~0.96 GB
// ---------------------------------------------------------------------------
__device__ float         g_S [(size_t)B_ * QT_ * KT_];    // logits (valid region only)
__device__ __nv_bfloat16 g_Qh[(size_t)B_ * QT_ * D_];
__device__ __nv_bfloat16 g_Ql[(size_t)B_ * QT_ * D_];
__device__ __nv_bfloat16 g_Kh[(size_t)B_ * KT_ * D_];
__device__ __nv_bfloat16 g_Kl[(size_t)B_ * KT_ * D_];
__device__ __nv_bfloat16 g_Ph[(size_t)B_ * QT_ * KT_];
__device__ __nv_bfloat16 g_Pl[(size_t)B_ * QT_ * KT_];
__device__ __nv_bfloat16 g_Vh[(size_t)B_ * D_ * KT_];     // V^T hi  [d][k]
__device__ __nv_bfloat16 g_Vl[(size_t)B_ * D_ * KT_];     // V^T lo
__device__ float         g_Vm[(size_t)B_ * D_];           // column mean of V

// ---------------------------------------------------------------------------
// Helpers (baseline sm_80+ features: cp.async, ldmatrix, mma.sync)
// ---------------------------------------------------------------------------
__device__ __forceinline__ uint32_t smem_u32(const void* p) {
    uint32_t a;
    asm("{ .reg .u64 t; cvta.to.shared.u64 t, %1; cvt.u32.u64 %0, t; }"
        : "=r"(a) : "l"(p));
    return a;
}
__device__ __forceinline__ void cpa16(uint32_t dst, const void* src) {
    asm volatile("cp.async.cg.shared.global [%0], [%1], 16;" :: "r"(dst), "l"(src));
}
#define CP_COMMIT() asm volatile("cp.async.commit_group;" ::: "memory")
#define CP_WAIT0()  asm volatile("cp.async.wait_group 0;" ::: "memory")

__device__ __forceinline__ void lm4(uint32_t* r, uint32_t addr) {
    asm volatile("ldmatrix.sync.aligned.m8n8.x4.shared.b16 {%0,%1,%2,%3}, [%4];"
                 : "=r"(r[0]), "=r"(r[1]), "=r"(r[2]), "=r"(r[3]) : "r"(addr));
}
__device__ __forceinline__ void mma16816(float* c, const uint32_t* a,
                                         uint32_t b0, uint32_t b1) {
    asm volatile(
        "mma.sync.aligned.m16n8k16.row.col.f32.bf16.bf16.f32 "
        "{%0,%1,%2,%3}, {%4,%5,%6,%7}, {%8,%9}, {%0,%1,%2,%3};"
        : "+f"(c[0]), "+f"(c[1]), "+f"(c[2]), "+f"(c[3])
        : "r"(a[0]), "r"(a[1]), "r"(a[2]), "r"(a[3]), "r"(b0), "r"(b1));
}

// ---------------------------------------------------------------------------
// bf16 split GEMM: C = (Ah+Al) @ (Bh+Bl)^T, dropping Al@Bl.
// Block 128x128, 8 warps (64x32 warp tiles), BK=32, double-buffered cp.async.
// MODE 1 = Q K^T : early-exit CTAs fully outside (ql, kl); plain epilogue.
// MODE 2 = P V   : clamp K-loop to ceil(kl/32); rows >= ql get Vmean.
// ---------------------------------------------------------------------------
#define PS   40                   // padded row stride (bf16 elems)
#define PART_BYTES (128 * PS * 2)
#define BUF_BYTES  (4 * PART_BYTES)

template <int MODE>
__global__ __launch_bounds__(256, 2)
void mma_gemm(const __nv_bfloat16* __restrict__ A0, const __nv_bfloat16* __restrict__ A1,
              const __nv_bfloat16* __restrict__ B0, const __nv_bfloat16* __restrict__ B1,
              float* __restrict__ C, int Kfull, int ldc,
              long strideA, long strideB, long strideC,
              const int* __restrict__ Qlen, const int* __restrict__ Klen,
              const float* __restrict__ Vmean)
{
    extern __shared__ char smem[];
    const uint32_t sb = smem_u32(smem);

    const int tid  = threadIdx.x;
    const int wid  = tid >> 5;
    const int lane = tid & 31;
    const int wm   = wid >> 2;
    const int wn   = wid & 3;
    const int bz   = blockIdx.z;
    const int n0   = blockIdx.x * 128;
    const int m0   = blockIdx.y * 128;

    const int ql = Qlen[bz];
    const int kl = Klen[bz];

    if (MODE == 1) {
        if (m0 >= ql || n0 >= kl) return;   // masked tile: never read downstream
    }

    const float* vm = (MODE == 2) ? (Vmean + (size_t)bz * D_) : nullptr;

    if (MODE == 2 && m0 >= ql) {
        // whole tile is invalid-q: O rows = column mean of V
        const int r  = tid >> 1;
        const int c0 = (tid & 1) * 64;
        float* orow = C + (size_t)bz * strideC + (size_t)(m0 + r) * ldc + n0 + c0;
        const float* vsrc = vm + n0 + c0;
        #pragma unroll
        for (int j = 0; j < 16; ++j)
            ((float4*)orow)[j] = ((const float4*)vsrc)[j];
        return;
    }

    const __nv_bfloat16* Ap[2] = { A0 + (size_t)bz * strideA, A1 + (size_t)bz * strideA };
    const __nv_bfloat16* Bp[2] = { B0 + (size_t)bz * strideB, B1 + (size_t)bz * strideB };

    const int ld_row0 = tid >> 2;
    const int ld_c    = (tid & 3) * 8;

    auto load_chunk = [&](int k0, int buf) {
        const uint32_t tb = sb + (uint32_t)buf * BUF_BYTES;
        #pragma unroll
        for (int p = 0; p < 2; ++p) {
            #pragma unroll
            for (int j = 0; j < 2; ++j) {
                const int r = ld_row0 + 64 * j;
                const uint32_t so = (uint32_t)(r * PS + ld_c) * 2;
                cpa16(tb + p * PART_BYTES + so,
                      Ap[p] + (size_t)(m0 + r) * Kfull + k0 + ld_c);
                cpa16(tb + (2 + p) * PART_BYTES + so,
                      Bp[p] + (size_t)(n0 + r) * Kfull + k0 + ld_c);
            }
        }
    };

    float acc[4][4][4];
    #pragma unroll
    for (int i = 0; i < 4; ++i)
        #pragma unroll
        for (int j = 0; j < 4; ++j)
            #pragma unroll
            for (int q = 0; q < 4; ++q) acc[i][j][q] = 0.f;

    int nchunks = Kfull / 32;
    if (MODE == 2) {
        const int nv = (kl + 31) >> 5;     // P is exactly 0 for k >= kl
        nchunks = nv < nchunks ? nv : nchunks;
    }

    load_chunk(0, 0);
    CP_COMMIT();

    const int a_row = (lane & 15);
    const int a_col = (lane >> 4) * 8;
    const int b_row = (lane & 7) + ((lane >> 4) << 3);
    const int b_col = (((lane >> 3) & 1) << 3);

    for (int t = 0; t < nchunks; ++t) {
        const int buf = t & 1;
        CP_WAIT0();
        __syncthreads();
        if (t + 1 < nchunks) {
            load_chunk((t + 1) * 32, buf ^ 1);
            CP_COMMIT();
        }

        const uint32_t tb  = sb + (uint32_t)buf * BUF_BYTES;
        const uint32_t Ah_ = tb;
        const uint32_t Al_ = tb + PART_BYTES;
        const uint32_t Bh_ = tb + 2 * PART_BYTES;
        const uint32_t Bl_ = tb + 3 * PART_BYTES;

        #pragma unroll
        for (int kk = 0; kk < 2; ++kk) {
            uint32_t bh[2][4], bl[2][4], a[4][4];
            #pragma unroll
            for (int np = 0; np < 2; ++np) {
                const uint32_t boff =
                    (uint32_t)((wn * 32 + np * 16 + b_row) * PS + kk * 16 + b_col) * 2;
                lm4(bh[np], Bh_ + boff);
                lm4(bl[np], Bl_ + boff);
            }
            #pragma unroll
            for (int mt = 0; mt < 4; ++mt)
                lm4(a[mt], Ah_ + (uint32_t)((wm * 64 + mt * 16 + a_row) * PS
                                            + kk * 16 + a_col) * 2);
            #pragma unroll
            for (int mt = 0; mt < 4; ++mt)
                #pragma unroll
                for (int nf = 0; nf < 4; ++nf) {
                    mma16816(acc[mt][nf], a[mt], bh[nf >> 1][(nf & 1) * 2],
                                                 bh[nf >> 1][(nf & 1) * 2 + 1]);
                    mma16816(acc[mt][nf], a[mt], bl[nf >> 1][(nf & 1) * 2],
                                                 bl[nf >> 1][(nf & 1) * 2 + 1]);
                }
            #pragma unroll
            for (int mt = 0; mt < 4; ++mt)
                lm4(a[mt], Al_ + (uint32_t)((wm * 64 + mt * 16 + a_row) * PS
                                            + kk * 16 + a_col) * 2);
            #pragma unroll
            for (int mt = 0; mt < 4; ++mt)
                #pragma unroll
                for (int nf = 0; nf < 4; ++nf)
                    mma16816(acc[mt][nf], a[mt], bh[nf >> 1][(nf & 1) * 2],
                                                 bh[nf >> 1][(nf & 1) * 2 + 1]);
        }
        __syncthreads();
    }

    float* Cb = C + (size_t)bz * strideC;
    #pragma unroll
    for (int mt = 0; mt < 4; ++mt) {
        #pragma unroll
        for (int nf = 0; nf < 4; ++nf) {
            const int n = n0 + wn * 32 + nf * 8 + (lane & 3) * 2;
            float2 vmn;
            if (MODE == 2) vmn = *(const float2*)(vm + n);
            #pragma unroll
            for (int h = 0; h < 2; ++h) {
                const int m = m0 + wm * 64 + mt * 16 + (lane >> 2) + h * 8;
                float2 v = make_float2(acc[mt][nf][h * 2], acc[mt][nf][h * 2 + 1]);
                if (MODE == 2 && m >= ql) v = vmn;
                *(float2*)(Cb + (size_t)m * ldc + n) = v;
            }
        }
    }
}

// ---------------------------------------------------------------------------
// 2-way bf16 split (elementwise)
// ---------------------------------------------------------------------------
__global__ __launch_bounds__(256)
void split2_k(const float* __restrict__ x, __nv_bfloat16* __restrict__ h,
              __nv_bfloat16* __restrict__ l)
{
    const size_t i = (size_t)blockIdx.x * blockDim.x + threadIdx.x;
    float4 v = ((const float4*)x)[i];
    float vv[4] = {v.x, v.y, v.z, v.w};
    __nv_bfloat16 hh[4], ll[4];
    #pragma unroll
    for (int j = 0; j < 4; ++j) {
        hh[j] = __float2bfloat16_rn(vv[j]);
        ll[j] = __float2bfloat16_rn(vv[j] - __bfloat162float(hh[j]));
    }
    ((__nv_bfloat162*)h)[2 * i + 0] = __nv_bfloat162(hh[0], hh[1]);
    ((__nv_bfloat162*)h)[2 * i + 1] = __nv_bfloat162(hh[2], hh[3]);
    ((__nv_bfloat162*)l)[2 * i + 0] = __nv_bfloat162(ll[0], ll[1]);
    ((__nv_bfloat162*)l)[2 * i + 1] = __nv_bfloat162(ll[2], ll[3]);
}

// ---------------------------------------------------------------------------
// V transpose + 2-way split: V[b][k][d] -> Vt{h,l}[b][d][k]
// ---------------------------------------------------------------------------
__global__ __launch_bounds__(256)
void vt_split2(const float* __restrict__ V, __nv_bfloat16* __restrict__ Th,
               __nv_bfloat16* __restrict__ Tl)
{
    __shared__ float tile[32][33];
    const int bz = blockIdx.z;
    const int d0 = blockIdx.x * 32;
    const int k0 = blockIdx.y * 32;
    const int tx = threadIdx.x, ty = threadIdx.y;
    const float* src = V + (size_t)bz * KT_ * D_;
    #pragma unroll
    for (int j = 0; j < 4; ++j)
        tile[ty + 8 * j][tx] = src[(size_t)(k0 + ty + 8 * j) * D_ + d0 + tx];
    __syncthreads();
    __nv_bfloat16* th = Th + (size_t)bz * D_ * KT_;
    __nv_bfloat16* tl = Tl + (size_t)bz * D_ * KT_;
    #pragma unroll
    for (int j = 0; j < 4; ++j) {
        const int d = d0 + ty + 8 * j;
        const float f = tile[tx][ty + 8 * j];
        const __nv_bfloat16 h = __float2bfloat16_rn(f);
        const __nv_bfloat16 l = __float2bfloat16_rn(f - __bfloat162float(h));
        th[(size_t)d * KT_ + k0 + tx] = h;
        tl[(size_t)d * KT_ + k0 + tx] = l;
    }
}

// ---------------------------------------------------------------------------
// Column mean of V: g_Vm[b][d] = (1/KT) * sum_k V[b][k][d]
// ---------------------------------------------------------------------------
__global__ __launch_bounds__(128)
void vmean_k(const float* __restrict__ V, float* __restrict__ M)
{
    const int b = blockIdx.y;
    const int d = blockIdx.x * 128 + threadIdx.x;
    const float* src = V + (size_t)b * KT_ * D_ + d;
    float a0 = 0.f, a1 = 0.f, a2 = 0.f, a3 = 0.f;
    for (int k = 0; k < KT_; k += 4) {
        a0 += src[(size_t)(k    ) * D_];
        a1 += src[(size_t)(k + 1) * D_];
        a2 += src[(size_t)(k + 2) * D_];
        a3 += src[(size_t)(k + 3) * D_];
    }
    M[(size_t)b * D_ + d] = ((a0 + a1) + (a2 + a3)) * (1.0f / KT_);
}

// ---------------------------------------------------------------------------
// Length-aware softmax + 2-way bf16 split of probabilities.
// Rows q >= ql: write zeros (GEMM2 substitutes Vmean). Columns k >= kl: zero.
// Thread tid owns contiguous elements [tid*8, tid*8+8).
// ---------------------------------------------------------------------------
__global__ __launch_bounds__(256)
void softmax_split(const float* __restrict__ S, __nv_bfloat16* __restrict__ Ph,
                   __nv_bfloat16* __restrict__ Pl,
                   const int* __restrict__ Qlen, const int* __restrict__ Klen)
{
    const size_t row = blockIdx.x;
    const int b = (int)(row / QT_);
    const int q = (int)(row % QT_);
    const int ql = Qlen[b];
    const int kl = Klen[b];
    const int tid = threadIdx.x, lane = tid & 31, wid = tid >> 5;

    __nv_bfloat162* ph = (__nv_bfloat162*)(Ph + row * KT_);
    __nv_bfloat162* pl = (__nv_bfloat162*)(Pl + row * KT_);

    if (q >= ql) {   // whole row masked -> P unused; write zeros for determinism
        const __nv_bfloat162 z = __float2bfloat162_rn(0.f);
        #pragma unroll
        for (int j = 0; j < 4; ++j) { ph[tid * 4 + j] = z; pl[tid * 4 + j] = z; }
        return;
    }

    __shared__ float red[8];
    const float* srow = S + row * KT_;
    const int base = tid * 8;

    float x[8];
    if (base + 8 <= kl) {
        float4 a = ((const float4*)srow)[tid * 2];
        float4 c = ((const float4*)srow)[tid * 2 + 1];
        x[0] = a.x; x[1] = a.y; x[2] = a.z; x[3] = a.w;
        x[4] = c.x; x[5] = c.y; x[6] = c.z; x[7] = c.w;
    } else {
        #pragma unroll
        for (int j = 0; j < 8; ++j)
            x[j] = (base + j < kl) ? srow[base + j] : -1e30f;  // never read masked S
    }

    float mx = fmaxf(fmaxf(fmaxf(x[0], x[1]), fmaxf(x[2], x[3])),
                     fmaxf(fmaxf(x[4], x[5]), fmaxf(x[6], x[7])));
    #pragma unroll
    for (int o = 16; o; o >>= 1) mx = fmaxf(mx, __shfl_xor_sync(~0u, mx, o));
    if (lane == 0) red[wid] = mx;
    __syncthreads();
    mx = red[0];
    #pragma unroll
    for (int i = 1; i < 8; ++i) mx = fmaxf(mx, red[i]);
    __syncthreads();

    float p[8];
    float s = 0.f;
    if (base < kl) {           // coherent branch: fully-masked chunks skip MUFU
        #pragma unroll
        for (int j = 0; j < 8; ++j) { p[j] = __expf(x[j] - mx); s += p[j]; }
    } else {
        #pragma unroll
        for (int j = 0; j < 8; ++j) p[j] = 0.f;
    }
    #pragma unroll
    for (int o = 16; o; o >>= 1) s += __shfl_xor_sync(~0u, s, o);
    if (lane == 0) red[wid] = s;
    __syncthreads();
    s = red[0];
    #pragma unroll
    for (int i = 1; i < 8; ++i) s += red[i];

    const float inv = 1.0f / s;
    __nv_bfloat16 hh[8], ll[8];
    #pragma unroll
    for (int j = 0; j < 8; ++j) {
        const float pv = p[j] * inv;
        hh[j] = __float2bfloat16_rn(pv);
        ll[j] = __float2bfloat16_rn(pv - __bfloat162float(hh[j]));
    }
    #pragma unroll
    for (int j = 0; j < 4; ++j) {
        ph[tid * 4 + j] = __nv_bfloat162(hh[2 * j], hh[2 * j + 1]);
        pl[tid * 4 + j] = __nv_bfloat162(ll[2 * j], ll[2 * j + 1]);
    }
}

// ---------------------------------------------------------------------------
// Launch pipeline (graph-capturable)
// ---------------------------------------------------------------------------
extern "C" void kernel_launch(void* const* d_in, const int* in_sizes, int n_in,
                              void* d_out, int out_size)
{
    const float* Q    = (const float*)d_in[0];
    const float* K    = (const float*)d_in[1];
    const float* V    = (const float*)d_in[2];
    const int*   Qlen = (const int*)d_in[3];
    const int*   Klen = (const int*)d_in[4];
    float*       O    = (float*)d_out;

    float *S, *Vm; __nv_bfloat16 *Qh, *Ql, *Kh, *Kl, *Ph, *Pl, *Vh, *Vl;
    cudaGetSymbolAddress((void**)&S,  g_S);
    cudaGetSymbolAddress((void**)&Vm, g_Vm);
    cudaGetSymbolAddress((void**)&Qh, g_Qh); cudaGetSymbolAddress((void**)&Ql, g_Ql);
    cudaGetSymbolAddress((void**)&Kh, g_Kh); cudaGetSymbolAddress((void**)&Kl, g_Kl);
    cudaGetSymbolAddress((void**)&Ph, g_Ph); cudaGetSymbolAddress((void**)&Pl, g_Pl);
    cudaGetSymbolAddress((void**)&Vh, g_Vh); cudaGetSymbolAddress((void**)&Vl, g_Vl);

    const int SMEM = 2 * BUF_BYTES;   // 81920
    cudaFuncSetAttribute(mma_gemm<1>, cudaFuncAttributeMaxDynamicSharedMemorySize, SMEM);
    cudaFuncSetAttribute(mma_gemm<2>, cudaFuncAttributeMaxDynamicSharedMemorySize, SMEM);

    const int nQ4 = (B_ * QT_ * D_) / 4;
    split2_k<<<nQ4 / 256, 256>>>(Q, Qh, Ql);
    split2_k<<<nQ4 / 256, 256>>>(K, Kh, Kl);
    vt_split2<<<dim3(D_ / 32, KT_ / 32, B_), dim3(32, 8)>>>(V, Vh, Vl);
    vmean_k<<<dim3(D_ / 128, B_), 128>>>(V, Vm);

    // GEMM1: S = Q K^T on valid tiles only
    mma_gemm<1><<<dim3(KT_ / 128, QT_ / 128, B_), 256, SMEM>>>(
        Qh, Ql, Kh, Kl, S, D_, KT_,
        (long)QT_ * D_, (long)KT_ * D_, (long)QT_ * KT_, Qlen, Klen, nullptr);

    // softmax + split P (length-aware)
    softmax_split<<<B_ * QT_, 256>>>(S, Ph, Pl, Qlen, Klen);

    // GEMM2: O = P V with K-loop clamped to kl; invalid-q rows get Vmean
    mma_gemm<2><<<dim3(D_ / 128, QT_ / 128, B_), 256, SMEM>>>(
        Ph, Pl, Vh, Vl, O, KT_, D_,
        (long)QT_ * KT_, (long)D_ * KT_, (long)QT_ * D_, Qlen, Klen, Vm);
}

// round 5
// speedup vs baseline: 7.6990x; 1.2345x over previous
#include <cuda_runtime.h>
#include <cuda_bf16.h>
#include <cstdint>
#include <cstddef>

#define B_   16
#define QT_  2048
#define KT_  2048
#define D_   1024
#define KSPLIT 16

// ---------------------------------------------------------------------------
// Scratch (device globals), ~0.96 GB
// ---------------------------------------------------------------------------
__device__ float         g_S [(size_t)B_ * QT_ * KT_];
__device__ __nv_bfloat16 g_Qh[(size_t)B_ * QT_ * D_];
__device__ __nv_bfloat16 g_Ql[(size_t)B_ * QT_ * D_];
__device__ __nv_bfloat16 g_Kh[(size_t)B_ * KT_ * D_];
__device__ __nv_bfloat16 g_Kl[(size_t)B_ * KT_ * D_];
__device__ __nv_bfloat16 g_Ph[(size_t)B_ * QT_ * KT_];
__device__ __nv_bfloat16 g_Pl[(size_t)B_ * QT_ * KT_];
__device__ __nv_bfloat16 g_Vh[(size_t)B_ * D_ * KT_];     // V^T hi  [d][k]
__device__ __nv_bfloat16 g_Vl[(size_t)B_ * D_ * KT_];     // V^T lo
__device__ float         g_Vp[(size_t)B_ * KSPLIT * D_];  // vmean partials
__device__ float         g_Vm[(size_t)B_ * D_];           // column mean of V

// ---------------------------------------------------------------------------
// Helpers
// ---------------------------------------------------------------------------
__device__ __forceinline__ uint32_t smem_u32(const void* p) {
    uint32_t a;
    asm("{ .reg .u64 t; cvta.to.shared.u64 t, %1; cvt.u32.u64 %0, t; }"
        : "=r"(a) : "l"(p));
    return a;
}
__device__ __forceinline__ void cpa16(uint32_t dst, const void* src) {
    asm volatile("cp.async.cg.shared.global [%0], [%1], 16;" :: "r"(dst), "l"(src));
}
#define CP_COMMIT() asm volatile("cp.async.commit_group;" ::: "memory")
#define CP_WAIT0()  asm volatile("cp.async.wait_group 0;" ::: "memory")

__device__ __forceinline__ void lm4(uint32_t* r, uint32_t addr) {
    asm volatile("ldmatrix.sync.aligned.m8n8.x4.shared.b16 {%0,%1,%2,%3}, [%4];"
                 : "=r"(r[0]), "=r"(r[1]), "=r"(r[2]), "=r"(r[3]) : "r"(addr));
}
__device__ __forceinline__ void mma16816(float* c, const uint32_t* a,
                                         uint32_t b0, uint32_t b1) {
    asm volatile(
        "mma.sync.aligned.m16n8k16.row.col.f32.bf16.bf16.f32 "
        "{%0,%1,%2,%3}, {%4,%5,%6,%7}, {%8,%9}, {%0,%1,%2,%3};"
        : "+f"(c[0]), "+f"(c[1]), "+f"(c[2]), "+f"(c[3])
        : "r"(a[0]), "r"(a[1]), "r"(a[2]), "r"(a[3]), "r"(b0), "r"(b1));
}

// ---------------------------------------------------------------------------
// bf16 split GEMM (unchanged proven core)
// ---------------------------------------------------------------------------
#define PS   40
#define PART_BYTES (128 * PS * 2)
#define BUF_BYTES  (4 * PART_BYTES)

template <int MODE>
__global__ __launch_bounds__(256, 2)
void mma_gemm(const __nv_bfloat16* __restrict__ A0, const __nv_bfloat16* __restrict__ A1,
              const __nv_bfloat16* __restrict__ B0, const __nv_bfloat16* __restrict__ B1,
              float* __restrict__ C, int Kfull, int ldc,
              long strideA, long strideB, long strideC,
              const int* __restrict__ Qlen, const int* __restrict__ Klen,
              const float* __restrict__ Vmean)
{
    extern __shared__ char smem[];
    const uint32_t sb = smem_u32(smem);

    const int tid  = threadIdx.x;
    const int wid  = tid >> 5;
    const int lane = tid & 31;
    const int wm   = wid >> 2;
    const int wn   = wid & 3;
    const int bz   = blockIdx.z;
    const int n0   = blockIdx.x * 128;
    const int m0   = blockIdx.y * 128;

    const int ql = Qlen[bz];
    const int kl = Klen[bz];

    if (MODE == 1) {
        if (m0 >= ql || n0 >= kl) return;
    }

    const float* vm = (MODE == 2) ? (Vmean + (size_t)bz * D_) : nullptr;

    if (MODE == 2 && m0 >= ql) {
        const int r  = tid >> 1;
        const int c0 = (tid & 1) * 64;
        float* orow = C + (size_t)bz * strideC + (size_t)(m0 + r) * ldc + n0 + c0;
        const float* vsrc = vm + n0 + c0;
        #pragma unroll
        for (int j = 0; j < 16; ++j)
            ((float4*)orow)[j] = ((const float4*)vsrc)[j];
        return;
    }

    const __nv_bfloat16* Ap[2] = { A0 + (size_t)bz * strideA, A1 + (size_t)bz * strideA };
    const __nv_bfloat16* Bp[2] = { B0 + (size_t)bz * strideB, B1 + (size_t)bz * strideB };

    const int ld_row0 = tid >> 2;
    const int ld_c    = (tid & 3) * 8;

    auto load_chunk = [&](int k0, int buf) {
        const uint32_t tb = sb + (uint32_t)buf * BUF_BYTES;
        #pragma unroll
        for (int p = 0; p < 2; ++p) {
            #pragma unroll
            for (int j = 0; j < 2; ++j) {
                const int r = ld_row0 + 64 * j;
                const uint32_t so = (uint32_t)(r * PS + ld_c) * 2;
                cpa16(tb + p * PART_BYTES + so,
                      Ap[p] + (size_t)(m0 + r) * Kfull + k0 + ld_c);
                cpa16(tb + (2 + p) * PART_BYTES + so,
                      Bp[p] + (size_t)(n0 + r) * Kfull + k0 + ld_c);
            }
        }
    };

    float acc[4][4][4];
    #pragma unroll
    for (int i = 0; i < 4; ++i)
        #pragma unroll
        for (int j = 0; j < 4; ++j)
            #pragma unroll
            for (int q = 0; q < 4; ++q) acc[i][j][q] = 0.f;

    int nchunks = Kfull / 32;
    if (MODE == 2) {
        const int nv = (kl + 31) >> 5;
        nchunks = nv < nchunks ? nv : nchunks;
    }

    load_chunk(0, 0);
    CP_COMMIT();

    const int a_row = (lane & 15);
    const int a_col = (lane >> 4) * 8;
    const int b_row = (lane & 7) + ((lane >> 4) << 3);
    const int b_col = (((lane >> 3) & 1) << 3);

    for (int t = 0; t < nchunks; ++t) {
        const int buf = t & 1;
        CP_WAIT0();
        __syncthreads();
        if (t + 1 < nchunks) {
            load_chunk((t + 1) * 32, buf ^ 1);
            CP_COMMIT();
        }

        const uint32_t tb  = sb + (uint32_t)buf * BUF_BYTES;
        const uint32_t Ah_ = tb;
        const uint32_t Al_ = tb + PART_BYTES;
        const uint32_t Bh_ = tb + 2 * PART_BYTES;
        const uint32_t Bl_ = tb + 3 * PART_BYTES;

        #pragma unroll
        for (int kk = 0; kk < 2; ++kk) {
            uint32_t bh[2][4], bl[2][4], a[4][4];
            #pragma unroll
            for (int np = 0; np < 2; ++np) {
                const uint32_t boff =
                    (uint32_t)((wn * 32 + np * 16 + b_row) * PS + kk * 16 + b_col) * 2;
                lm4(bh[np], Bh_ + boff);
                lm4(bl[np], Bl_ + boff);
            }
            #pragma unroll
            for (int mt = 0; mt < 4; ++mt)
                lm4(a[mt], Ah_ + (uint32_t)((wm * 64 + mt * 16 + a_row) * PS
                                            + kk * 16 + a_col) * 2);
            #pragma unroll
            for (int mt = 0; mt < 4; ++mt)
                #pragma unroll
                for (int nf = 0; nf < 4; ++nf) {
                    mma16816(acc[mt][nf], a[mt], bh[nf >> 1][(nf & 1) * 2],
                                                 bh[nf >> 1][(nf & 1) * 2 + 1]);
                    mma16816(acc[mt][nf], a[mt], bl[nf >> 1][(nf & 1) * 2],
                                                 bl[nf >> 1][(nf & 1) * 2 + 1]);
                }
            #pragma unroll
            for (int mt = 0; mt < 4; ++mt)
                lm4(a[mt], Al_ + (uint32_t)((wm * 64 + mt * 16 + a_row) * PS
                                            + kk * 16 + a_col) * 2);
            #pragma unroll
            for (int mt = 0; mt < 4; ++mt)
                #pragma unroll
                for (int nf = 0; nf < 4; ++nf)
                    mma16816(acc[mt][nf], a[mt], bh[nf >> 1][(nf & 1) * 2],
                                                 bh[nf >> 1][(nf & 1) * 2 + 1]);
        }
        __syncthreads();
    }

    float* Cb = C + (size_t)bz * strideC;
    #pragma unroll
    for (int mt = 0; mt < 4; ++mt) {
        #pragma unroll
        for (int nf = 0; nf < 4; ++nf) {
            const int n = n0 + wn * 32 + nf * 8 + (lane & 3) * 2;
            float2 vmn;
            if (MODE == 2) vmn = *(const float2*)(vm + n);
            #pragma unroll
            for (int h = 0; h < 2; ++h) {
                const int m = m0 + wm * 64 + mt * 16 + (lane >> 2) + h * 8;
                float2 v = make_float2(acc[mt][nf][h * 2], acc[mt][nf][h * 2 + 1]);
                if (MODE == 2 && m >= ql) v = vmn;
                *(float2*)(Cb + (size_t)m * ldc + n) = v;
            }
        }
    }
}

// ---------------------------------------------------------------------------
// Length-aware 2-way bf16 split: one block per row; skip rows never read by
// the GEMM (>= ceil128(len), tile-skip boundary).
// ---------------------------------------------------------------------------
__global__ __launch_bounds__(256)
void split2_rows(const float* __restrict__ x, __nv_bfloat16* __restrict__ h,
                 __nv_bfloat16* __restrict__ l, const int* __restrict__ Len)
{
    const int b   = blockIdx.y;
    const int row = blockIdx.x;
    if (row >= ((Len[b] + 127) & ~127)) return;
    const size_t i = ((size_t)b * QT_ + row) * (D_ / 4) + threadIdx.x;
    float4 v = ((const float4*)x)[i];
    float vv[4] = {v.x, v.y, v.z, v.w};
    __nv_bfloat16 hh[4], ll[4];
    #pragma unroll
    for (int j = 0; j < 4; ++j) {
        hh[j] = __float2bfloat16_rn(vv[j]);
        ll[j] = __float2bfloat16_rn(vv[j] - __bfloat162float(hh[j]));
    }
    ((__nv_bfloat162*)h)[2 * i + 0] = __nv_bfloat162(hh[0], hh[1]);
    ((__nv_bfloat162*)h)[2 * i + 1] = __nv_bfloat162(hh[2], hh[3]);
    ((__nv_bfloat162*)l)[2 * i + 0] = __nv_bfloat162(ll[0], ll[1]);
    ((__nv_bfloat162*)l)[2 * i + 1] = __nv_bfloat162(ll[2], ll[3]);
}

// ---------------------------------------------------------------------------
// V transpose + split, skipping k-tiles >= ceil32(kl) (never read by GEMM2)
// ---------------------------------------------------------------------------
__global__ __launch_bounds__(256)
void vt_split2(const float* __restrict__ V, __nv_bfloat16* __restrict__ Th,
               __nv_bfloat16* __restrict__ Tl, const int* __restrict__ Klen)
{
    const int bz = blockIdx.z;
    const int k0 = blockIdx.y * 32;
    if (k0 >= ((Klen[bz] + 31) & ~31)) return;
    __shared__ float tile[32][33];
    const int d0 = blockIdx.x * 32;
    const int tx = threadIdx.x, ty = threadIdx.y;
    const float* src = V + (size_t)bz * KT_ * D_;
    #pragma unroll
    for (int j = 0; j < 4; ++j)
        tile[ty + 8 * j][tx] = src[(size_t)(k0 + ty + 8 * j) * D_ + d0 + tx];
    __syncthreads();
    __nv_bfloat16* th = Th + (size_t)bz * D_ * KT_;
    __nv_bfloat16* tl = Tl + (size_t)bz * D_ * KT_;
    #pragma unroll
    for (int j = 0; j < 4; ++j) {
        const int d = d0 + ty + 8 * j;
        const float f = tile[tx][ty + 8 * j];
        const __nv_bfloat16 h = __float2bfloat16_rn(f);
        const __nv_bfloat16 l = __float2bfloat16_rn(f - __bfloat162float(h));
        th[(size_t)d * KT_ + k0 + tx] = h;
        tl[(size_t)d * KT_ + k0 + tx] = l;
    }
}

// ---------------------------------------------------------------------------
// vmean in two stages: 2048-block partial sums, then reduce 16 partials.
// (Mean is over ALL KT rows — matches the reference's uniform-row semantics.)
// ---------------------------------------------------------------------------
__global__ __launch_bounds__(128)
void vmean_part(const float* __restrict__ V, float* __restrict__ P)
{
    const int b  = blockIdx.z;
    const int ks = blockIdx.y;
    const int d  = blockIdx.x * 128 + threadIdx.x;
    const float* src = V + (size_t)b * KT_ * D_ + (size_t)ks * (KT_ / KSPLIT) * D_ + d;
    float a0 = 0.f, a1 = 0.f, a2 = 0.f, a3 = 0.f;
    #pragma unroll 4
    for (int k = 0; k < KT_ / KSPLIT; k += 4) {
        a0 += src[(size_t)(k    ) * D_];
        a1 += src[(size_t)(k + 1) * D_];
        a2 += src[(size_t)(k + 2) * D_];
        a3 += src[(size_t)(k + 3) * D_];
    }
    P[((size_t)b * KSPLIT + ks) * D_ + d] = (a0 + a1) + (a2 + a3);
}

__global__ __launch_bounds__(256)
void vmean_red(const float* __restrict__ P, float* __restrict__ M)
{
    const int idx = blockIdx.x * 256 + threadIdx.x;   // over B_*D_
    const int b = idx / D_, d = idx % D_;
    const float* p = P + (size_t)b * KSPLIT * D_ + d;
    float s = 0.f;
    #pragma unroll
    for (int i = 0; i < KSPLIT; ++i) s += p[(size_t)i * D_];
    M[idx] = s * (1.0f / KT_);
}

// ---------------------------------------------------------------------------
// Length-aware softmax + split; writes clamped to k < ceil32(kl), and rows
// >= ceil128(ql) skipped entirely (never read by GEMM2).
// ---------------------------------------------------------------------------
__global__ __launch_bounds__(256)
void softmax_split(const float* __restrict__ S, __nv_bfloat16* __restrict__ Ph,
                   __nv_bfloat16* __restrict__ Pl,
                   const int* __restrict__ Qlen, const int* __restrict__ Klen)
{
    const size_t row = blockIdx.x;
    const int b = (int)(row / QT_);
    const int q = (int)(row % QT_);
    const int ql = Qlen[b];
    const int kl = Klen[b];
    const int kend = (kl + 31) & ~31;                 // GEMM2 read bound
    const int tid = threadIdx.x, lane = tid & 31, wid = tid >> 5;
    const int base = tid * 8;

    if (q >= ((ql + 127) & ~127)) return;             // never read

    __nv_bfloat162* ph = (__nv_bfloat162*)(Ph + row * KT_);
    __nv_bfloat162* pl = (__nv_bfloat162*)(Pl + row * KT_);

    if (q >= ql) {                                    // read as A in boundary tile
        if (base < kend) {
            const __nv_bfloat162 z = __float2bfloat162_rn(0.f);
            #pragma unroll
            for (int j = 0; j < 4; ++j) { ph[tid * 4 + j] = z; pl[tid * 4 + j] = z; }
        }
        return;
    }

    __shared__ float red[8];
    const float* srow = S + row * KT_;

    float x[8];
    if (base + 8 <= kl) {
        float4 a = ((const float4*)srow)[tid * 2];
        float4 c = ((const float4*)srow)[tid * 2 + 1];
        x[0] = a.x; x[1] = a.y; x[2] = a.z; x[3] = a.w;
        x[4] = c.x; x[5] = c.y; x[6] = c.z; x[7] = c.w;
    } else {
        #pragma unroll
        for (int j = 0; j < 8; ++j)
            x[j] = (base + j < kl) ? srow[base + j] : -1e30f;
    }

    float mx = fmaxf(fmaxf(fmaxf(x[0], x[1]), fmaxf(x[2], x[3])),
                     fmaxf(fmaxf(x[4], x[5]), fmaxf(x[6], x[7])));
    #pragma unroll
    for (int o = 16; o; o >>= 1) mx = fmaxf(mx, __shfl_xor_sync(~0u, mx, o));
    if (lane == 0) red[wid] = mx;
    __syncthreads();
    mx = red[0];
    #pragma unroll
    for (int i = 1; i < 8; ++i) mx = fmaxf(mx, red[i]);
    __syncthreads();

    float p[8];
    float s = 0.f;
    if (base < kl) {
        #pragma unroll
        for (int j = 0; j < 8; ++j) { p[j] = __expf(x[j] - mx); s += p[j]; }
    } else {
        #pragma unroll
        for (int j = 0; j < 8; ++j) p[j] = 0.f;
    }
    #pragma unroll
    for (int o = 16; o; o >>= 1) s += __shfl_xor_sync(~0u, s, o);
    if (lane == 0) red[wid] = s;
    __syncthreads();
    s = red[0];
    #pragma unroll
    for (int i = 1; i < 8; ++i) s += red[i];

    if (base >= kend) return;                         // beyond GEMM2 read bound

    const float inv = 1.0f / s;
    __nv_bfloat16 hh[8], ll[8];
    #pragma unroll
    for (int j = 0; j < 8; ++j) {
        const float pv = p[j] * inv;
        hh[j] = __float2bfloat16_rn(pv);
        ll[j] = __float2bfloat16_rn(pv - __bfloat162float(hh[j]));
    }
    #pragma unroll
    for (int j = 0; j < 4; ++j) {
        ph[tid * 4 + j] = __nv_bfloat162(hh[2 * j], hh[2 * j + 1]);
        pl[tid * 4 + j] = __nv_bfloat162(ll[2 * j], ll[2 * j + 1]);
    }
}

// ---------------------------------------------------------------------------
// Launch pipeline
// ---------------------------------------------------------------------------
extern "C" void kernel_launch(void* const* d_in, const int* in_sizes, int n_in,
                              void* d_out, int out_size)
{
    const float* Q    = (const float*)d_in[0];
    const float* K    = (const float*)d_in[1];
    const float* V    = (const float*)d_in[2];
    const int*   Qlen = (const int*)d_in[3];
    const int*   Klen = (const int*)d_in[4];
    float*       O    = (float*)d_out;

    float *S, *Vm, *Vp; __nv_bfloat16 *Qh, *Ql, *Kh, *Kl, *Ph, *Pl, *Vh, *Vl;
    cudaGetSymbolAddress((void**)&S,  g_S);
    cudaGetSymbolAddress((void**)&Vm, g_Vm);
    cudaGetSymbolAddress((void**)&Vp, g_Vp);
    cudaGetSymbolAddress((void**)&Qh, g_Qh); cudaGetSymbolAddress((void**)&Ql, g_Ql);
    cudaGetSymbolAddress((void**)&Kh, g_Kh); cudaGetSymbolAddress((void**)&Kl, g_Kl);
    cudaGetSymbolAddress((void**)&Ph, g_Ph); cudaGetSymbolAddress((void**)&Pl, g_Pl);
    cudaGetSymbolAddress((void**)&Vh, g_Vh); cudaGetSymbolAddress((void**)&Vl, g_Vl);

    const int SMEM = 2 * BUF_BYTES;
    cudaFuncSetAttribute(mma_gemm<1>, cudaFuncAttributeMaxDynamicSharedMemorySize, SMEM);
    cudaFuncSetAttribute(mma_gemm<2>, cudaFuncAttributeMaxDynamicSharedMemorySize, SMEM);

    split2_rows<<<dim3(QT_, B_), 256>>>(Q, Qh, Ql, Qlen);
    split2_rows<<<dim3(KT_, B_), 256>>>(K, Kh, Kl, Klen);
    vt_split2<<<dim3(D_ / 32, KT_ / 32, B_), dim3(32, 8)>>>(V, Vh, Vl, Klen);
    vmean_part<<<dim3(D_ / 128, KSPLIT, B_), 128>>>(V, Vp);
    vmean_red<<<(B_ * D_) / 256, 256>>>(Vp, Vm);

    mma_gemm<1><<<dim3(KT_ / 128, QT_ / 128, B_), 256, SMEM>>>(
        Qh, Ql, Kh, Kl, S, D_, KT_,
        (long)QT_ * D_, (long)KT_ * D_, (long)QT_ * KT_, Qlen, Klen, nullptr);

    softmax_split<<<B_ * QT_, 256>>>(S, Ph, Pl, Qlen, Klen);

    mma_gemm<2><<<dim3(D_ / 128, QT_ / 128, B_), 256, SMEM>>>(
        Ph, Pl, Vh, Vl, O, KT_, D_,
        (long)QT_ * KT_, (long)D_ * KT_, (long)QT_ * D_, Qlen, Klen, Vm);
}

// round 6
// speedup vs baseline: 8.7461x; 1.1360x over previous
#include <cuda_runtime.h>
#include <cuda_bf16.h>
#include <cstdint>
#include <cstddef>

#define B_   16
#define QT_  2048
#define KT_  2048
#define D_   1024
#define KSPLIT 16

// ---------------------------------------------------------------------------
// Scratch (device globals), ~0.96 GB
// ---------------------------------------------------------------------------
__device__ float         g_S [(size_t)B_ * QT_ * KT_];
__device__ __nv_bfloat16 g_Qh[(size_t)B_ * QT_ * D_];
__device__ __nv_bfloat16 g_Ql[(size_t)B_ * QT_ * D_];
__device__ __nv_bfloat16 g_Kh[(size_t)B_ * KT_ * D_];
__device__ __nv_bfloat16 g_Kl[(size_t)B_ * KT_ * D_];
__device__ __nv_bfloat16 g_Ph[(size_t)B_ * QT_ * KT_];
__device__ __nv_bfloat16 g_Pl[(size_t)B_ * QT_ * KT_];
__device__ __nv_bfloat16 g_Vh[(size_t)B_ * D_ * KT_];
__device__ __nv_bfloat16 g_Vl[(size_t)B_ * D_ * KT_];
__device__ float         g_Vp[(size_t)B_ * KSPLIT * D_];
__device__ float         g_Vm[(size_t)B_ * D_];

// ---------------------------------------------------------------------------
// Helpers
// ---------------------------------------------------------------------------
__device__ __forceinline__ uint32_t smem_u32(const void* p) {
    uint32_t a;
    asm("{ .reg .u64 t; cvta.to.shared.u64 t, %1; cvt.u32.u64 %0, t; }"
        : "=r"(a) : "l"(p));
    return a;
}
__device__ __forceinline__ void cpa16(uint32_t dst, const void* src) {
    asm volatile("cp.async.cg.shared.global [%0], [%1], 16;" :: "r"(dst), "l"(src));
}
#define CP_COMMIT() asm volatile("cp.async.commit_group;" ::: "memory")
#define CP_WAIT0()  asm volatile("cp.async.wait_group 0;" ::: "memory")
#define CP_WAIT1()  asm volatile("cp.async.wait_group 1;" ::: "memory")

__device__ __forceinline__ void lm4(uint32_t* r, uint32_t addr) {
    asm volatile("ldmatrix.sync.aligned.m8n8.x4.shared.b16 {%0,%1,%2,%3}, [%4];"
                 : "=r"(r[0]), "=r"(r[1]), "=r"(r[2]), "=r"(r[3]) : "r"(addr));
}
__device__ __forceinline__ void mma16816(float* c, const uint32_t* a,
                                         uint32_t b0, uint32_t b1) {
    asm volatile(
        "mma.sync.aligned.m16n8k16.row.col.f32.bf16.bf16.f32 "
        "{%0,%1,%2,%3}, {%4,%5,%6,%7}, {%8,%9}, {%0,%1,%2,%3};"
        : "+f"(c[0]), "+f"(c[1]), "+f"(c[2]), "+f"(c[3])
        : "r"(a[0]), "r"(a[1]), "r"(a[2]), "r"(a[3]), "r"(b0), "r"(b1));
}

// ---------------------------------------------------------------------------
// bf16 split GEMM, now swizzled smem (no padding) + 3-stage cp.async pipeline.
// Tile layout per 128x32 part: row r (64 bytes) split into four 16B chunks;
// chunk c stored at c ^ ((r>>1)&3). Conflict-free for ldmatrix 8-row phases.
// ---------------------------------------------------------------------------
#define PART_BYTES 8192               // 128 rows * 64 B
#define BUF_BYTES  (4 * PART_BYTES)   // Ah, Al, Bh, Bl
#define NSTAGE 3

template <int MODE>
__global__ __launch_bounds__(256, 2)
void mma_gemm(const __nv_bfloat16* __restrict__ A0, const __nv_bfloat16* __restrict__ A1,
              const __nv_bfloat16* __restrict__ B0, const __nv_bfloat16* __restrict__ B1,
              float* __restrict__ C, int Kfull, int ldc,
              long strideA, long strideB, long strideC,
              const int* __restrict__ Qlen, const int* __restrict__ Klen,
              const float* __restrict__ Vmean)
{
    extern __shared__ char smem[];
    const uint32_t sb = smem_u32(smem);

    const int tid  = threadIdx.x;
    const int wid  = tid >> 5;
    const int lane = tid & 31;
    const int wm   = wid >> 2;
    const int wn   = wid & 3;
    const int bz   = blockIdx.z;
    const int n0   = blockIdx.x * 128;
    const int m0   = blockIdx.y * 128;

    const int ql = Qlen[bz];
    const int kl = Klen[bz];

    if (MODE == 1) {
        if (m0 >= ql || n0 >= kl) return;
    }

    const float* vm = (MODE == 2) ? (Vmean + (size_t)bz * D_) : nullptr;

    if (MODE == 2 && m0 >= ql) {
        const int r  = tid >> 1;
        const int c0 = (tid & 1) * 64;
        float* orow = C + (size_t)bz * strideC + (size_t)(m0 + r) * ldc + n0 + c0;
        const float* vsrc = vm + n0 + c0;
        #pragma unroll
        for (int j = 0; j < 16; ++j)
            ((float4*)orow)[j] = ((const float4*)vsrc)[j];
        return;
    }

    const __nv_bfloat16* Ap[2] = { A0 + (size_t)bz * strideA, A1 + (size_t)bz * strideA };
    const __nv_bfloat16* Bp[2] = { B0 + (size_t)bz * strideB, B1 + (size_t)bz * strideB };

    const int ld_row0 = tid >> 2;            // rows r and r+64
    const int ld_ck   = tid & 3;             // 16B chunk index within row
    const int ld_c    = ld_ck * 8;           // element offset

    auto load_chunk = [&](int k0, int slot) {
        const uint32_t tb = sb + (uint32_t)slot * BUF_BYTES;
        #pragma unroll
        for (int p = 0; p < 2; ++p) {
            #pragma unroll
            for (int j = 0; j < 2; ++j) {
                const int r = ld_row0 + 64 * j;
                const uint32_t so =
                    (uint32_t)(r * 64 + ((ld_ck ^ ((r >> 1) & 3)) * 16));
                cpa16(tb + p * PART_BYTES + so,
                      Ap[p] + (size_t)(m0 + r) * Kfull + k0 + ld_c);
                cpa16(tb + (2 + p) * PART_BYTES + so,
                      Bp[p] + (size_t)(n0 + r) * Kfull + k0 + ld_c);
            }
        }
    };

    float acc[4][4][4];
    #pragma unroll
    for (int i = 0; i < 4; ++i)
        #pragma unroll
        for (int j = 0; j < 4; ++j)
            #pragma unroll
            for (int q = 0; q < 4; ++q) acc[i][j][q] = 0.f;

    int nchunks = Kfull / 32;
    if (MODE == 2) {
        const int nv = (kl + 31) >> 5;
        nchunks = nv < nchunks ? nv : nchunks;
    }

    load_chunk(0, 0);
    CP_COMMIT();
    if (nchunks > 1) { load_chunk(32, 1); CP_COMMIT(); }

    const int a_row = (lane & 15);
    const int a_hi  = (lane >> 4);           // 16B sub-chunk select
    const int b_row = (lane & 7) + ((lane >> 4) << 3);
    const int b_hi  = ((lane >> 3) & 1);

    for (int t = 0; t < nchunks; ++t) {
        if (t + 1 < nchunks) CP_WAIT1(); else CP_WAIT0();
        __syncthreads();
        if (t + 2 < nchunks) {
            load_chunk((t + 2) * 32, (t + 2) % NSTAGE);
            CP_COMMIT();
        }

        const uint32_t tb  = sb + (uint32_t)(t % NSTAGE) * BUF_BYTES;
        const uint32_t Ah_ = tb;
        const uint32_t Al_ = tb + PART_BYTES;
        const uint32_t Bh_ = tb + 2 * PART_BYTES;
        const uint32_t Bl_ = tb + 3 * PART_BYTES;

        #pragma unroll
        for (int kk = 0; kk < 2; ++kk) {
            uint32_t bh[2][4], bl[2][4], a[4][4];
            uint32_t aoff[4];
            #pragma unroll
            for (int np = 0; np < 2; ++np) {
                const int row = wn * 32 + np * 16 + b_row;
                const uint32_t boff =
                    (uint32_t)(row * 64 + (((kk * 2 + b_hi) ^ ((row >> 1) & 3)) * 16));
                lm4(bh[np], Bh_ + boff);
                lm4(bl[np], Bl_ + boff);
            }
            #pragma unroll
            for (int mt = 0; mt < 4; ++mt) {
                const int row = wm * 64 + mt * 16 + a_row;
                aoff[mt] =
                    (uint32_t)(row * 64 + (((kk * 2 + a_hi) ^ ((row >> 1) & 3)) * 16));
                lm4(a[mt], Ah_ + aoff[mt]);
            }
            #pragma unroll
            for (int mt = 0; mt < 4; ++mt)
                #pragma unroll
                for (int nf = 0; nf < 4; ++nf) {
                    mma16816(acc[mt][nf], a[mt], bh[nf >> 1][(nf & 1) * 2],
                                                 bh[nf >> 1][(nf & 1) * 2 + 1]);
                    mma16816(acc[mt][nf], a[mt], bl[nf >> 1][(nf & 1) * 2],
                                                 bl[nf >> 1][(nf & 1) * 2 + 1]);
                }
            #pragma unroll
            for (int mt = 0; mt < 4; ++mt)
                lm4(a[mt], Al_ + aoff[mt]);
            #pragma unroll
            for (int mt = 0; mt < 4; ++mt)
                #pragma unroll
                for (int nf = 0; nf < 4; ++nf)
                    mma16816(acc[mt][nf], a[mt], bh[nf >> 1][(nf & 1) * 2],
                                                 bh[nf >> 1][(nf & 1) * 2 + 1]);
        }
    }

    float* Cb = C + (size_t)bz * strideC;
    #pragma unroll
    for (int mt = 0; mt < 4; ++mt) {
        #pragma unroll
        for (int nf = 0; nf < 4; ++nf) {
            const int n = n0 + wn * 32 + nf * 8 + (lane & 3) * 2;
            float2 vmn;
            if (MODE == 2) vmn = *(const float2*)(vm + n);
            #pragma unroll
            for (int h = 0; h < 2; ++h) {
                const int m = m0 + wm * 64 + mt * 16 + (lane >> 2) + h * 8;
                float2 v = make_float2(acc[mt][nf][h * 2], acc[mt][nf][h * 2 + 1]);
                if (MODE == 2 && m >= ql) v = vmn;
                *(float2*)(Cb + (size_t)m * ldc + n) = v;
            }
        }
    }
}

// ---------------------------------------------------------------------------
// Length-aware 2-way bf16 split (rows beyond ceil128(len) skipped)
// ---------------------------------------------------------------------------
__global__ __launch_bounds__(256)
void split2_rows(const float* __restrict__ x, __nv_bfloat16* __restrict__ h,
                 __nv_bfloat16* __restrict__ l, const int* __restrict__ Len)
{
    const int b   = blockIdx.y;
    const int row = blockIdx.x;
    if (row >= ((Len[b] + 127) & ~127)) return;
    const size_t i = ((size_t)b * QT_ + row) * (D_ / 4) + threadIdx.x;
    float4 v = ((const float4*)x)[i];
    float vv[4] = {v.x, v.y, v.z, v.w};
    __nv_bfloat16 hh[4], ll[4];
    #pragma unroll
    for (int j = 0; j < 4; ++j) {
        hh[j] = __float2bfloat16_rn(vv[j]);
        ll[j] = __float2bfloat16_rn(vv[j] - __bfloat162float(hh[j]));
    }
    ((__nv_bfloat162*)h)[2 * i + 0] = __nv_bfloat162(hh[0], hh[1]);
    ((__nv_bfloat162*)h)[2 * i + 1] = __nv_bfloat162(hh[2], hh[3]);
    ((__nv_bfloat162*)l)[2 * i + 0] = __nv_bfloat162(ll[0], ll[1]);
    ((__nv_bfloat162*)l)[2 * i + 1] = __nv_bfloat162(ll[2], ll[3]);
}

// ---------------------------------------------------------------------------
// V transpose + split (k-tiles beyond ceil32(kl) skipped)
// ---------------------------------------------------------------------------
__global__ __launch_bounds__(256)
void vt_split2(const float* __restrict__ V, __nv_bfloat16* __restrict__ Th,
               __nv_bfloat16* __restrict__ Tl, const int* __restrict__ Klen)
{
    const int bz = blockIdx.z;
    const int k0 = blockIdx.y * 32;
    if (k0 >= ((Klen[bz] + 31) & ~31)) return;
    __shared__ float tile[32][33];
    const int d0 = blockIdx.x * 32;
    const int tx = threadIdx.x, ty = threadIdx.y;
    const float* src = V + (size_t)bz * KT_ * D_;
    #pragma unroll
    for (int j = 0; j < 4; ++j)
        tile[ty + 8 * j][tx] = src[(size_t)(k0 + ty + 8 * j) * D_ + d0 + tx];
    __syncthreads();
    __nv_bfloat16* th = Th + (size_t)bz * D_ * KT_;
    __nv_bfloat16* tl = Tl + (size_t)bz * D_ * KT_;
    #pragma unroll
    for (int j = 0; j < 4; ++j) {
        const int d = d0 + ty + 8 * j;
        const float f = tile[tx][ty + 8 * j];
        const __nv_bfloat16 h = __float2bfloat16_rn(f);
        const __nv_bfloat16 l = __float2bfloat16_rn(f - __bfloat162float(h));
        th[(size_t)d * KT_ + k0 + tx] = h;
        tl[(size_t)d * KT_ + k0 + tx] = l;
    }
}

// ---------------------------------------------------------------------------
// vmean two-stage
// ---------------------------------------------------------------------------
__global__ __launch_bounds__(128)
void vmean_part(const float* __restrict__ V, float* __restrict__ P)
{
    const int b  = blockIdx.z;
    const int ks = blockIdx.y;
    const int d  = blockIdx.x * 128 + threadIdx.x;
    const float* src = V + (size_t)b * KT_ * D_ + (size_t)ks * (KT_ / KSPLIT) * D_ + d;
    float a0 = 0.f, a1 = 0.f, a2 = 0.f, a3 = 0.f;
    #pragma unroll 4
    for (int k = 0; k < KT_ / KSPLIT; k += 4) {
        a0 += src[(size_t)(k    ) * D_];
        a1 += src[(size_t)(k + 1) * D_];
        a2 += src[(size_t)(k + 2) * D_];
        a3 += src[(size_t)(k + 3) * D_];
    }
    P[((size_t)b * KSPLIT + ks) * D_ + d] = (a0 + a1) + (a2 + a3);
}

__global__ __launch_bounds__(256)
void vmean_red(const float* __restrict__ P, float* __restrict__ M)
{
    const int idx = blockIdx.x * 256 + threadIdx.x;
    const int b = idx / D_, d = idx % D_;
    const float* p = P + (size_t)b * KSPLIT * D_ + d;
    float s = 0.f;
    #pragma unroll
    for (int i = 0; i < KSPLIT; ++i) s += p[(size_t)i * D_];
    M[idx] = s * (1.0f / KT_);
}

// ---------------------------------------------------------------------------
// Length-aware softmax + split
// ---------------------------------------------------------------------------
__global__ __launch_bounds__(256)
void softmax_split(const float* __restrict__ S, __nv_bfloat16* __restrict__ Ph,
                   __nv_bfloat16* __restrict__ Pl,
                   const int* __restrict__ Qlen, const int* __restrict__ Klen)
{
    const size_t row = blockIdx.x;
    const int b = (int)(row / QT_);
    const int q = (int)(row % QT_);
    const int ql = Qlen[b];
    const int kl = Klen[b];
    const int kend = (kl + 31) & ~31;
    const int tid = threadIdx.x, lane = tid & 31, wid = tid >> 5;
    const int base = tid * 8;

    if (q >= ((ql + 127) & ~127)) return;

    __nv_bfloat162* ph = (__nv_bfloat162*)(Ph + row * KT_);
    __nv_bfloat162* pl = (__nv_bfloat162*)(Pl + row * KT_);

    if (q >= ql) {
        if (base < kend) {
            const __nv_bfloat162 z = __float2bfloat162_rn(0.f);
            #pragma unroll
            for (int j = 0; j < 4; ++j) { ph[tid * 4 + j] = z; pl[tid * 4 + j] = z; }
        }
        return;
    }

    __shared__ float red[8];
    const float* srow = S + row * KT_;

    float x[8];
    if (base + 8 <= kl) {
        float4 a = ((const float4*)srow)[tid * 2];
        float4 c = ((const float4*)srow)[tid * 2 + 1];
        x[0] = a.x; x[1] = a.y; x[2] = a.z; x[3] = a.w;
        x[4] = c.x; x[5] = c.y; x[6] = c.z; x[7] = c.w;
    } else {
        #pragma unroll
        for (int j = 0; j < 8; ++j)
            x[j] = (base + j < kl) ? srow[base + j] : -1e30f;
    }

    float mx = fmaxf(fmaxf(fmaxf(x[0], x[1]), fmaxf(x[2], x[3])),
                     fmaxf(fmaxf(x[4], x[5]), fmaxf(x[6], x[7])));
    #pragma unroll
    for (int o = 16; o; o >>= 1) mx = fmaxf(mx, __shfl_xor_sync(~0u, mx, o));
    if (lane == 0) red[wid] = mx;
    __syncthreads();
    mx = red[0];
    #pragma unroll
    for (int i = 1; i < 8; ++i) mx = fmaxf(mx, red[i]);
    __syncthreads();

    float p[8];
    float s = 0.f;
    if (base < kl) {
        #pragma unroll
        for (int j = 0; j < 8; ++j) { p[j] = __expf(x[j] - mx); s += p[j]; }
    } else {
        #pragma unroll
        for (int j = 0; j < 8; ++j) p[j] = 0.f;
    }
    #pragma unroll
    for (int o = 16; o; o >>= 1) s += __shfl_xor_sync(~0u, s, o);
    if (lane == 0) red[wid] = s;
    __syncthreads();
    s = red[0];
    #pragma unroll
    for (int i = 1; i < 8; ++i) s += red[i];

    if (base >= kend) return;

    const float inv = 1.0f / s;
    __nv_bfloat16 hh[8], ll[8];
    #pragma unroll
    for (int j = 0; j < 8; ++j) {
        const float pv = p[j] * inv;
        hh[j] = __float2bfloat16_rn(pv);
        ll[j] = __float2bfloat16_rn(pv - __bfloat162float(hh[j]));
    }
    #pragma unroll
    for (int j = 0; j < 4; ++j) {
        ph[tid * 4 + j] = __nv_bfloat162(hh[2 * j], hh[2 * j + 1]);
        pl[tid * 4 + j] = __nv_bfloat162(ll[2 * j], ll[2 * j + 1]);
    }
}

// ---------------------------------------------------------------------------
// Launch pipeline
// ---------------------------------------------------------------------------
extern "C" void kernel_launch(void* const* d_in, const int* in_sizes, int n_in,
                              void* d_out, int out_size)
{
    const float* Q    = (const float*)d_in[0];
    const float* K    = (const float*)d_in[1];
    const float* V    = (const float*)d_in[2];
    const int*   Qlen = (const int*)d_in[3];
    const int*   Klen = (const int*)d_in[4];
    float*       O    = (float*)d_out;

    float *S, *Vm, *Vp; __nv_bfloat16 *Qh, *Ql, *Kh, *Kl, *Ph, *Pl, *Vh, *Vl;
    cudaGetSymbolAddress((void**)&S,  g_S);
    cudaGetSymbolAddress((void**)&Vm, g_Vm);
    cudaGetSymbolAddress((void**)&Vp, g_Vp);
    cudaGetSymbolAddress((void**)&Qh, g_Qh); cudaGetSymbolAddress((void**)&Ql, g_Ql);
    cudaGetSymbolAddress((void**)&Kh, g_Kh); cudaGetSymbolAddress((void**)&Kl, g_Kl);
    cudaGetSymbolAddress((void**)&Ph, g_Ph); cudaGetSymbolAddress((void**)&Pl, g_Pl);
    cudaGetSymbolAddress((void**)&Vh, g_Vh); cudaGetSymbolAddress((void**)&Vl, g_Vl);

    const int SMEM = NSTAGE * BUF_BYTES;   // 98304
    cudaFuncSetAttribute(mma_gemm<1>, cudaFuncAttributeMaxDynamicSharedMemorySize, SMEM);
    cudaFuncSetAttribute(mma_gemm<2>, cudaFuncAttributeMaxDynamicSharedMemorySize, SMEM);

    split2_rows<<<dim3(QT_, B_), 256>>>(Q, Qh, Ql, Qlen);
    split2_rows<<<dim3(KT_, B_), 256>>>(K, Kh, Kl, Klen);
    vt_split2<<<dim3(D_ / 32, KT_ / 32, B_), dim3(32, 8)>>>(V, Vh, Vl, Klen);
    vmean_part<<<dim3(D_ / 128, KSPLIT, B_), 128>>>(V, Vp);
    vmean_red<<<(B_ * D_) / 256, 256>>>(Vp, Vm);

    mma_gemm<1><<<dim3(KT_ / 128, QT_ / 128, B_), 256, SMEM>>>(
        Qh, Ql, Kh, Kl, S, D_, KT_,
        (long)QT_ * D_, (long)KT_ * D_, (long)QT_ * KT_, Qlen, Klen, nullptr);

    softmax_split<<<B_ * QT_, 256>>>(S, Ph, Pl, Qlen, Klen);

    mma_gemm<2><<<dim3(D_ / 128, QT_ / 128, B_), 256, SMEM>>>(
        Ph, Pl, Vh, Vl, O, KT_, D_,
        (long)QT_ * KT_, (long)D_ * KT_, (long)QT_ * D_, Qlen, Klen, Vm);
}

// round 7
// speedup vs baseline: 8.7882x; 1.0048x over previous
#include <cuda_runtime.h>
#include <cuda_bf16.h>
#include <cstdint>
#include <cstddef>

#define B_   16
#define QT_  2048
#define KT_  2048
#define D_   1024
#define KSPLIT 16

// ---------------------------------------------------------------------------
// Scratch (device globals), ~0.96 GB
// ---------------------------------------------------------------------------
__device__ float         g_S [(size_t)B_ * QT_ * KT_];
__device__ __nv_bfloat16 g_Qh[(size_t)B_ * QT_ * D_];
__device__ __nv_bfloat16 g_Ql[(size_t)B_ * QT_ * D_];
__device__ __nv_bfloat16 g_Kh[(size_t)B_ * KT_ * D_];
__device__ __nv_bfloat16 g_Kl[(size_t)B_ * KT_ * D_];
__device__ __nv_bfloat16 g_Ph[(size_t)B_ * QT_ * KT_];
__device__ __nv_bfloat16 g_Pl[(size_t)B_ * QT_ * KT_];
__device__ __nv_bfloat16 g_Vh[(size_t)B_ * D_ * KT_];
__device__ __nv_bfloat16 g_Vl[(size_t)B_ * D_ * KT_];
__device__ float         g_Vp[(size_t)B_ * KSPLIT * D_];
__device__ float         g_Vm[(size_t)B_ * D_];

// ---------------------------------------------------------------------------
// Helpers
// ---------------------------------------------------------------------------
__device__ __forceinline__ uint32_t smem_u32(const void* p) {
    uint32_t a;
    asm("{ .reg .u64 t; cvta.to.shared.u64 t, %1; cvt.u32.u64 %0, t; }"
        : "=r"(a) : "l"(p));
    return a;
}
__device__ __forceinline__ void cpa16(uint32_t dst, const void* src) {
    asm volatile("cp.async.cg.shared.global [%0], [%1], 16;" :: "r"(dst), "l"(src));
}
#define CP_COMMIT() asm volatile("cp.async.commit_group;" ::: "memory")
#define CP_WAIT0()  asm volatile("cp.async.wait_group 0;" ::: "memory")
#define CP_WAIT1()  asm volatile("cp.async.wait_group 1;" ::: "memory")

__device__ __forceinline__ void lm4(uint32_t* r, uint32_t addr) {
    asm volatile("ldmatrix.sync.aligned.m8n8.x4.shared.b16 {%0,%1,%2,%3}, [%4];"
                 : "=r"(r[0]), "=r"(r[1]), "=r"(r[2]), "=r"(r[3]) : "r"(addr));
}
__device__ __forceinline__ void mma16816(float* c, const uint32_t* a,
                                         uint32_t b0, uint32_t b1) {
    asm volatile(
        "mma.sync.aligned.m16n8k16.row.col.f32.bf16.bf16.f32 "
        "{%0,%1,%2,%3}, {%4,%5,%6,%7}, {%8,%9}, {%0,%1,%2,%3};"
        : "+f"(c[0]), "+f"(c[1]), "+f"(c[2]), "+f"(c[3])
        : "r"(a[0]), "r"(a[1]), "r"(a[2]), "r"(a[3]), "r"(b0), "r"(b1));
}

// ---------------------------------------------------------------------------
// bf16 split GEMM, swizzled smem + 3-stage cp.async pipeline (proven core)
// ---------------------------------------------------------------------------
#define PART_BYTES 8192
#define BUF_BYTES  (4 * PART_BYTES)
#define NSTAGE 3

template <int MODE>
__global__ __launch_bounds__(256, 2)
void mma_gemm(const __nv_bfloat16* __restrict__ A0, const __nv_bfloat16* __restrict__ A1,
              const __nv_bfloat16* __restrict__ B0, const __nv_bfloat16* __restrict__ B1,
              float* __restrict__ C, int Kfull, int ldc,
              long strideA, long strideB, long strideC,
              const int* __restrict__ Qlen, const int* __restrict__ Klen,
              const float* __restrict__ Vmean)
{
    extern __shared__ char smem[];
    const uint32_t sb = smem_u32(smem);

    const int tid  = threadIdx.x;
    const int wid  = tid >> 5;
    const int lane = tid & 31;
    const int wm   = wid >> 2;
    const int wn   = wid & 3;
    const int bz   = blockIdx.z;
    const int n0   = blockIdx.x * 128;
    const int m0   = blockIdx.y * 128;

    const int ql = Qlen[bz];
    const int kl = Klen[bz];

    if (MODE == 1) {
        if (m0 >= ql || n0 >= kl) return;
    }

    const float* vm = (MODE == 2) ? (Vmean + (size_t)bz * D_) : nullptr;

    if (MODE == 2 && m0 >= ql) {
        const int r  = tid >> 1;
        const int c0 = (tid & 1) * 64;
        float* orow = C + (size_t)bz * strideC + (size_t)(m0 + r) * ldc + n0 + c0;
        const float* vsrc = vm + n0 + c0;
        #pragma unroll
        for (int j = 0; j < 16; ++j)
            ((float4*)orow)[j] = ((const float4*)vsrc)[j];
        return;
    }

    const __nv_bfloat16* Ap[2] = { A0 + (size_t)bz * strideA, A1 + (size_t)bz * strideA };
    const __nv_bfloat16* Bp[2] = { B0 + (size_t)bz * strideB, B1 + (size_t)bz * strideB };

    const int ld_row0 = tid >> 2;
    const int ld_ck   = tid & 3;
    const int ld_c    = ld_ck * 8;

    auto load_chunk = [&](int k0, int slot) {
        const uint32_t tb = sb + (uint32_t)slot * BUF_BYTES;
        #pragma unroll
        for (int p = 0; p < 2; ++p) {
            #pragma unroll
            for (int j = 0; j < 2; ++j) {
                const int r = ld_row0 + 64 * j;
                const uint32_t so =
                    (uint32_t)(r * 64 + ((ld_ck ^ ((r >> 1) & 3)) * 16));
                cpa16(tb + p * PART_BYTES + so,
                      Ap[p] + (size_t)(m0 + r) * Kfull + k0 + ld_c);
                cpa16(tb + (2 + p) * PART_BYTES + so,
                      Bp[p] + (size_t)(n0 + r) * Kfull + k0 + ld_c);
            }
        }
    };

    float acc[4][4][4];
    #pragma unroll
    for (int i = 0; i < 4; ++i)
        #pragma unroll
        for (int j = 0; j < 4; ++j)
            #pragma unroll
            for (int q = 0; q < 4; ++q) acc[i][j][q] = 0.f;

    int nchunks = Kfull / 32;
    if (MODE == 2) {
        const int nv = (kl + 31) >> 5;
        nchunks = nv < nchunks ? nv : nchunks;
    }

    load_chunk(0, 0);
    CP_COMMIT();
    if (nchunks > 1) { load_chunk(32, 1); CP_COMMIT(); }

    const int a_row = (lane & 15);
    const int a_hi  = (lane >> 4);
    const int b_row = (lane & 7) + ((lane >> 4) << 3);
    const int b_hi  = ((lane >> 3) & 1);

    for (int t = 0; t < nchunks; ++t) {
        if (t + 1 < nchunks) CP_WAIT1(); else CP_WAIT0();
        __syncthreads();
        if (t + 2 < nchunks) {
            load_chunk((t + 2) * 32, (t + 2) % NSTAGE);
            CP_COMMIT();
        }

        const uint32_t tb  = sb + (uint32_t)(t % NSTAGE) * BUF_BYTES;
        const uint32_t Ah_ = tb;
        const uint32_t Al_ = tb + PART_BYTES;
        const uint32_t Bh_ = tb + 2 * PART_BYTES;
        const uint32_t Bl_ = tb + 3 * PART_BYTES;

        #pragma unroll
        for (int kk = 0; kk < 2; ++kk) {
            uint32_t bh[2][4], bl[2][4], a[4][4];
            uint32_t aoff[4];
            #pragma unroll
            for (int np = 0; np < 2; ++np) {
                const int row = wn * 32 + np * 16 + b_row;
                const uint32_t boff =
                    (uint32_t)(row * 64 + (((kk * 2 + b_hi) ^ ((row >> 1) & 3)) * 16));
                lm4(bh[np], Bh_ + boff);
                lm4(bl[np], Bl_ + boff);
            }
            #pragma unroll
            for (int mt = 0; mt < 4; ++mt) {
                const int row = wm * 64 + mt * 16 + a_row;
                aoff[mt] =
                    (uint32_t)(row * 64 + (((kk * 2 + a_hi) ^ ((row >> 1) & 3)) * 16));
                lm4(a[mt], Ah_ + aoff[mt]);
            }
            #pragma unroll
            for (int mt = 0; mt < 4; ++mt)
                #pragma unroll
                for (int nf = 0; nf < 4; ++nf) {
                    mma16816(acc[mt][nf], a[mt], bh[nf >> 1][(nf & 1) * 2],
                                                 bh[nf >> 1][(nf & 1) * 2 + 1]);
                    mma16816(acc[mt][nf], a[mt], bl[nf >> 1][(nf & 1) * 2],
                                                 bl[nf >> 1][(nf & 1) * 2 + 1]);
                }
            #pragma unroll
            for (int mt = 0; mt < 4; ++mt)
                lm4(a[mt], Al_ + aoff[mt]);
            #pragma unroll
            for (int mt = 0; mt < 4; ++mt)
                #pragma unroll
                for (int nf = 0; nf < 4; ++nf)
                    mma16816(acc[mt][nf], a[mt], bh[nf >> 1][(nf & 1) * 2],
                                                 bh[nf >> 1][(nf & 1) * 2 + 1]);
        }
    }

    float* Cb = C + (size_t)bz * strideC;
    #pragma unroll
    for (int mt = 0; mt < 4; ++mt) {
        #pragma unroll
        for (int nf = 0; nf < 4; ++nf) {
            const int n = n0 + wn * 32 + nf * 8 + (lane & 3) * 2;
            float2 vmn;
            if (MODE == 2) vmn = *(const float2*)(vm + n);
            #pragma unroll
            for (int h = 0; h < 2; ++h) {
                const int m = m0 + wm * 64 + mt * 16 + (lane >> 2) + h * 8;
                float2 v = make_float2(acc[mt][nf][h * 2], acc[mt][nf][h * 2 + 1]);
                if (MODE == 2 && m >= ql) v = vmn;
                *(float2*)(Cb + (size_t)m * ldc + n) = v;
            }
        }
    }
}

// ---------------------------------------------------------------------------
// Merged length-aware split for Q and K (one launch): grid.y in [0,32),
// sel = y>>4 (0=Q, 1=K), b = y&15. Rows beyond ceil128(len) skipped.
// ---------------------------------------------------------------------------
__global__ __launch_bounds__(256)
void split2_qk(const float* __restrict__ Q, const float* __restrict__ K,
               __nv_bfloat16* __restrict__ Qh, __nv_bfloat16* __restrict__ Ql,
               __nv_bfloat16* __restrict__ Kh, __nv_bfloat16* __restrict__ Kl,
               const int* __restrict__ Qlen, const int* __restrict__ Klen)
{
    const int y   = blockIdx.y;
    const int sel = y >> 4;
    const int b   = y & 15;
    const int row = blockIdx.x;
    const float* x = sel ? K : Q;
    __nv_bfloat16* h = sel ? Kh : Qh;
    __nv_bfloat16* l = sel ? Kl : Ql;
    const int len = sel ? Klen[b] : Qlen[b];
    if (row >= ((len + 127) & ~127)) return;
    const size_t i = ((size_t)b * QT_ + row) * (D_ / 4) + threadIdx.x;
    float4 v = ((const float4*)x)[i];
    float vv[4] = {v.x, v.y, v.z, v.w};
    __nv_bfloat16 hh[4], ll[4];
    #pragma unroll
    for (int j = 0; j < 4; ++j) {
        hh[j] = __float2bfloat16_rn(vv[j]);
        ll[j] = __float2bfloat16_rn(vv[j] - __bfloat162float(hh[j]));
    }
    ((__nv_bfloat162*)h)[2 * i + 0] = __nv_bfloat162(hh[0], hh[1]);
    ((__nv_bfloat162*)h)[2 * i + 1] = __nv_bfloat162(hh[2], hh[3]);
    ((__nv_bfloat162*)l)[2 * i + 0] = __nv_bfloat162(ll[0], ll[1]);
    ((__nv_bfloat162*)l)[2 * i + 1] = __nv_bfloat162(ll[2], ll[3]);
}

// ---------------------------------------------------------------------------
// V transpose + split (k-tiles beyond ceil32(kl) skipped)
// ---------------------------------------------------------------------------
__global__ __launch_bounds__(256)
void vt_split2(const float* __restrict__ V, __nv_bfloat16* __restrict__ Th,
               __nv_bfloat16* __restrict__ Tl, const int* __restrict__ Klen)
{
    const int bz = blockIdx.z;
    const int k0 = blockIdx.y * 32;
    if (k0 >= ((Klen[bz] + 31) & ~31)) return;
    __shared__ float tile[32][33];
    const int d0 = blockIdx.x * 32;
    const int tx = threadIdx.x, ty = threadIdx.y;
    const float* src = V + (size_t)bz * KT_ * D_;
    #pragma unroll
    for (int j = 0; j < 4; ++j)
        tile[ty + 8 * j][tx] = src[(size_t)(k0 + ty + 8 * j) * D_ + d0 + tx];
    __syncthreads();
    __nv_bfloat16* th = Th + (size_t)bz * D_ * KT_;
    __nv_bfloat16* tl = Tl + (size_t)bz * D_ * KT_;
    #pragma unroll
    for (int j = 0; j < 4; ++j) {
        const int d = d0 + ty + 8 * j;
        const float f = tile[tx][ty + 8 * j];
        const __nv_bfloat16 h = __float2bfloat16_rn(f);
        const __nv_bfloat16 l = __float2bfloat16_rn(f - __bfloat162float(h));
        th[(size_t)d * KT_ + k0 + tx] = h;
        tl[(size_t)d * KT_ + k0 + tx] = l;
    }
}

// ---------------------------------------------------------------------------
// vmean two-stage (over ALL KT rows — matches uniform-row semantics)
// ---------------------------------------------------------------------------
__global__ __launch_bounds__(128)
void vmean_part(const float* __restrict__ V, float* __restrict__ P)
{
    const int b  = blockIdx.z;
    const int ks = blockIdx.y;
    const int d  = blockIdx.x * 128 + threadIdx.x;
    const float* src = V + (size_t)b * KT_ * D_ + (size_t)ks * (KT_ / KSPLIT) * D_ + d;
    float a0 = 0.f, a1 = 0.f, a2 = 0.f, a3 = 0.f;
    #pragma unroll 4
    for (int k = 0; k < KT_ / KSPLIT; k += 4) {
        a0 += src[(size_t)(k    ) * D_];
        a1 += src[(size_t)(k + 1) * D_];
        a2 += src[(size_t)(k + 2) * D_];
        a3 += src[(size_t)(k + 3) * D_];
    }
    P[((size_t)b * KSPLIT + ks) * D_ + d] = (a0 + a1) + (a2 + a3);
}

__global__ __launch_bounds__(256)
void vmean_red(const float* __restrict__ P, float* __restrict__ M)
{
    const int idx = blockIdx.x * 256 + threadIdx.x;
    const int b = idx / D_, d = idx % D_;
    const float* p = P + (size_t)b * KSPLIT * D_ + d;
    float s = 0.f;
    #pragma unroll
    for (int i = 0; i < KSPLIT; ++i) s += p[(size_t)i * D_];
    M[idx] = s * (1.0f / KT_);
}

// ---------------------------------------------------------------------------
// Length-aware softmax + split
// ---------------------------------------------------------------------------
__global__ __launch_bounds__(256)
void softmax_split(const float* __restrict__ S, __nv_bfloat16* __restrict__ Ph,
                   __nv_bfloat16* __restrict__ Pl,
                   const int* __restrict__ Qlen, const int* __restrict__ Klen)
{
    const size_t row = blockIdx.x;
    const int b = (int)(row / QT_);
    const int q = (int)(row % QT_);
    const int ql = Qlen[b];
    const int kl = Klen[b];
    const int kend = (kl + 31) & ~31;
    const int tid = threadIdx.x, lane = tid & 31, wid = tid >> 5;
    const int base = tid * 8;

    if (q >= ((ql + 127) & ~127)) return;

    __nv_bfloat162* ph = (__nv_bfloat162*)(Ph + row * KT_);
    __nv_bfloat162* pl = (__nv_bfloat162*)(Pl + row * KT_);

    if (q >= ql) {
        if (base < kend) {
            const __nv_bfloat162 z = __float2bfloat162_rn(0.f);
            #pragma unroll
            for (int j = 0; j < 4; ++j) { ph[tid * 4 + j] = z; pl[tid * 4 + j] = z; }
        }
        return;
    }

    __shared__ float red[8];
    const float* srow = S + row * KT_;

    float x[8];
    if (base + 8 <= kl) {
        float4 a = ((const float4*)srow)[tid * 2];
        float4 c = ((const float4*)srow)[tid * 2 + 1];
        x[0] = a.x; x[1] = a.y; x[2] = a.z; x[3] = a.w;
        x[4] = c.x; x[5] = c.y; x[6] = c.z; x[7] = c.w;
    } else {
        #pragma unroll
        for (int j = 0; j < 8; ++j)
            x[j] = (base + j < kl) ? srow[base + j] : -1e30f;
    }

    float mx = fmaxf(fmaxf(fmaxf(x[0], x[1]), fmaxf(x[2], x[3])),
                     fmaxf(fmaxf(x[4], x[5]), fmaxf(x[6], x[7])));
    #pragma unroll
    for (int o = 16; o; o >>= 1) mx = fmaxf(mx, __shfl_xor_sync(~0u, mx, o));
    if (lane == 0) red[wid] = mx;
    __syncthreads();
    mx = red[0];
    #pragma unroll
    for (int i = 1; i < 8; ++i) mx = fmaxf(mx, red[i]);
    __syncthreads();

    float p[8];
    float s = 0.f;
    if (base < kl) {
        #pragma unroll
        for (int j = 0; j < 8; ++j) { p[j] = __expf(x[j] - mx); s += p[j]; }
    } else {
        #pragma unroll
        for (int j = 0; j < 8; ++j) p[j] = 0.f;
    }
    #pragma unroll
    for (int o = 16; o; o >>= 1) s += __shfl_xor_sync(~0u, s, o);
    if (lane == 0) red[wid] = s;
    __syncthreads();
    s = red[0];
    #pragma unroll
    for (int i = 1; i < 8; ++i) s += red[i];

    if (base >= kend) return;

    const float inv = 1.0f / s;
    __nv_bfloat16 hh[8], ll[8];
    #pragma unroll
    for (int j = 0; j < 8; ++j) {
        const float pv = p[j] * inv;
        hh[j] = __float2bfloat16_rn(pv);
        ll[j] = __float2bfloat16_rn(pv - __bfloat162float(hh[j]));
    }
    #pragma unroll
    for (int j = 0; j < 4; ++j) {
        ph[tid * 4 + j] = __nv_bfloat162(hh[2 * j], hh[2 * j + 1]);
        pl[tid * 4 + j] = __nv_bfloat162(ll[2 * j], ll[2 * j + 1]);
    }
}

// ---------------------------------------------------------------------------
// Launch pipeline. Dual-stream fork/join: the V-path (transpose/split/mean)
// runs on a side stream concurrent with GEMM1 + softmax; GEMM2 joins both.
// Stream/events are created lazily on the first (eager) call, so creation
// never happens inside graph capture; the captured graph contains the
// cross-stream dependencies and replays identically.
// ---------------------------------------------------------------------------
extern "C" void kernel_launch(void* const* d_in, const int* in_sizes, int n_in,
                              void* d_out, int out_size)
{
    const float* Q    = (const float*)d_in[0];
    const float* K    = (const float*)d_in[1];
    const float* V    = (const float*)d_in[2];
    const int*   Qlen = (const int*)d_in[3];
    const int*   Klen = (const int*)d_in[4];
    float*       O    = (float*)d_out;

    float *S, *Vm, *Vp; __nv_bfloat16 *Qh, *Ql, *Kh, *Kl, *Ph, *Pl, *Vh, *Vl;
    cudaGetSymbolAddress((void**)&S,  g_S);
    cudaGetSymbolAddress((void**)&Vm, g_Vm);
    cudaGetSymbolAddress((void**)&Vp, g_Vp);
    cudaGetSymbolAddress((void**)&Qh, g_Qh); cudaGetSymbolAddress((void**)&Ql, g_Ql);
    cudaGetSymbolAddress((void**)&Kh, g_Kh); cudaGetSymbolAddress((void**)&Kl, g_Kl);
    cudaGetSymbolAddress((void**)&Ph, g_Ph); cudaGetSymbolAddress((void**)&Pl, g_Pl);
    cudaGetSymbolAddress((void**)&Vh, g_Vh); cudaGetSymbolAddress((void**)&Vl, g_Vl);

    static cudaStream_t s2 = nullptr;
    static cudaEvent_t evRoot = nullptr, evV = nullptr;
    if (s2 == nullptr) {
        cudaStreamCreateWithFlags(&s2, cudaStreamNonBlocking);
        cudaEventCreateWithFlags(&evRoot, cudaEventDisableTiming);
        cudaEventCreateWithFlags(&evV,    cudaEventDisableTiming);
    }

    const int SMEM = NSTAGE * BUF_BYTES;   // 98304
    cudaFuncSetAttribute(mma_gemm<1>, cudaFuncAttributeMaxDynamicSharedMemorySize, SMEM);
    cudaFuncSetAttribute(mma_gemm<2>, cudaFuncAttributeMaxDynamicSharedMemorySize, SMEM);

    // Fork: V-path on side stream
    cudaEventRecord(evRoot, 0);
    cudaStreamWaitEvent(s2, evRoot, 0);
    vt_split2<<<dim3(D_ / 32, KT_ / 32, B_), dim3(32, 8), 0, s2>>>(V, Vh, Vl, Klen);
    vmean_part<<<dim3(D_ / 128, KSPLIT, B_), 128, 0, s2>>>(V, Vp);
    vmean_red<<<(B_ * D_) / 256, 256, 0, s2>>>(Vp, Vm);
    cudaEventRecord(evV, s2);

    // Main stream: Q/K split -> GEMM1 -> softmax
    split2_qk<<<dim3(QT_, 32), 256>>>(Q, K, Qh, Ql, Kh, Kl, Qlen, Klen);

    mma_gemm<1><<<dim3(KT_ / 128, QT_ / 128, B_), 256, SMEM>>>(
        Qh, Ql, Kh, Kl, S, D_, KT_,
        (long)QT_ * D_, (long)KT_ * D_, (long)QT_ * KT_, Qlen, Klen, nullptr);

    softmax_split<<<B_ * QT_, 256>>>(S, Ph, Pl, Qlen, Klen);

    // Join: GEMM2 needs the V-path
    cudaStreamWaitEvent(0, evV, 0);
    mma_gemm<2><<<dim3(D_ / 128, QT_ / 128, B_), 256, SMEM>>>(
        Ph, Pl, Vh, Vl, O, KT_, D_,
        (long)QT_ * KT_, (long)D_ * KT_, (long)QT_ * D_, Qlen, Klen, Vm);
}

// round 9
// speedup vs baseline: 9.0869x; 1.0340x over previous
#include <cuda_runtime.h>
#include <cuda_bf16.h>
#include <cstdint>
#include <cstddef>

#define B_   16
#define QT_  2048
#define KT_  2048
#define D_   1024
#define KSPLIT 16

// ---------------------------------------------------------------------------
// Scratch (device globals), ~0.96 GB
// ---------------------------------------------------------------------------
__device__ float         g_S [(size_t)B_ * QT_ * KT_];
__device__ __nv_bfloat16 g_Qh[(size_t)B_ * QT_ * D_];
__device__ __nv_bfloat16 g_Ql[(size_t)B_ * QT_ * D_];
__device__ __nv_bfloat16 g_Kh[(size_t)B_ * KT_ * D_];
__device__ __nv_bfloat16 g_Kl[(size_t)B_ * KT_ * D_];
__device__ __nv_bfloat16 g_Ph[(size_t)B_ * QT_ * KT_];
__device__ __nv_bfloat16 g_Pl[(size_t)B_ * QT_ * KT_];
__device__ __nv_bfloat16 g_Vh[(size_t)B_ * D_ * KT_];
__device__ __nv_bfloat16 g_Vl[(size_t)B_ * D_ * KT_];
__device__ float         g_Vp[(size_t)B_ * KSPLIT * D_];
__device__ float         g_Vm[(size_t)B_ * D_];

// ---------------------------------------------------------------------------
// Helpers
// ---------------------------------------------------------------------------
__device__ __forceinline__ uint32_t smem_u32(const void* p) {
    uint32_t a;
    asm("{ .reg .u64 t; cvta.to.shared.u64 t, %1; cvt.u32.u64 %0, t; }"
        : "=r"(a) : "l"(p));
    return a;
}
__device__ __forceinline__ void cpa16(uint32_t dst, const void* src) {
    asm volatile("cp.async.cg.shared.global [%0], [%1], 16;" :: "r"(dst), "l"(src));
}
#define CP_COMMIT() asm volatile("cp.async.commit_group;" ::: "memory")
#define CP_WAIT0()  asm volatile("cp.async.wait_group 0;" ::: "memory")
#define CP_WAIT1()  asm volatile("cp.async.wait_group 1;" ::: "memory")

__device__ __forceinline__ void lm4(uint32_t* r, uint32_t addr) {
    asm volatile("ldmatrix.sync.aligned.m8n8.x4.shared.b16 {%0,%1,%2,%3}, [%4];"
                 : "=r"(r[0]), "=r"(r[1]), "=r"(r[2]), "=r"(r[3]) : "r"(addr));
}
__device__ __forceinline__ void mma16816(float* c, const uint32_t* a,
                                         uint32_t b0, uint32_t b1) {
    asm volatile(
        "mma.sync.aligned.m16n8k16.row.col.f32.bf16.bf16.f32 "
        "{%0,%1,%2,%3}, {%4,%5,%6,%7}, {%8,%9}, {%0,%1,%2,%3};"
        : "+f"(c[0]), "+f"(c[1]), "+f"(c[2]), "+f"(c[3])
        : "r"(a[0]), "r"(a[1]), "r"(a[2]), "r"(a[3]), "r"(b0), "r"(b1));
}

// ---------------------------------------------------------------------------
// bf16 split GEMM, swizzled smem + 3-stage cp.async pipeline (proven core)
// ---------------------------------------------------------------------------
#define PART_BYTES 8192
#define BUF_BYTES  (4 * PART_BYTES)
#define NSTAGE 3

template <int MODE>
__global__ __launch_bounds__(256, 2)
void mma_gemm(const __nv_bfloat16* __restrict__ A0, const __nv_bfloat16* __restrict__ A1,
              const __nv_bfloat16* __restrict__ B0, const __nv_bfloat16* __restrict__ B1,
              float* __restrict__ C, int Kfull, int ldc,
              long strideA, long strideB, long strideC,
              const int* __restrict__ Qlen, const int* __restrict__ Klen,
              const float* __restrict__ Vmean)
{
    extern __shared__ char smem[];
    const uint32_t sb = smem_u32(smem);

    const int tid  = threadIdx.x;
    const int wid  = tid >> 5;
    const int lane = tid & 31;
    const int wm   = wid >> 2;
    const int wn   = wid & 3;
    const int bz   = blockIdx.z;
    const int n0   = blockIdx.x * 128;
    const int m0   = blockIdx.y * 128;

    const int ql = Qlen[bz];
    const int kl = Klen[bz];

    if (MODE == 1) {
        if (m0 >= ql || n0 >= kl) return;
    }

    const float* vm = (MODE == 2) ? (Vmean + (size_t)bz * D_) : nullptr;

    if (MODE == 2 && m0 >= ql) {
        const int r  = tid >> 1;
        const int c0 = (tid & 1) * 64;
        float* orow = C + (size_t)bz * strideC + (size_t)(m0 + r) * ldc + n0 + c0;
        const float* vsrc = vm + n0 + c0;
        #pragma unroll
        for (int j = 0; j < 16; ++j)
            ((float4*)orow)[j] = ((const float4*)vsrc)[j];
        return;
    }

    const __nv_bfloat16* Ap[2] = { A0 + (size_t)bz * strideA, A1 + (size_t)bz * strideA };
    const __nv_bfloat16* Bp[2] = { B0 + (size_t)bz * strideB, B1 + (size_t)bz * strideB };

    const int ld_row0 = tid >> 2;
    const int ld_ck   = tid & 3;
    const int ld_c    = ld_ck * 8;

    auto load_chunk = [&](int k0, int slot) {
        const uint32_t tb = sb + (uint32_t)slot * BUF_BYTES;
        #pragma unroll
        for (int p = 0; p < 2; ++p) {
            #pragma unroll
            for (int j = 0; j < 2; ++j) {
                const int r = ld_row0 + 64 * j;
                const uint32_t so =
                    (uint32_t)(r * 64 + ((ld_ck ^ ((r >> 1) & 3)) * 16));
                cpa16(tb + p * PART_BYTES + so,
                      Ap[p] + (size_t)(m0 + r) * Kfull + k0 + ld_c);
                cpa16(tb + (2 + p) * PART_BYTES + so,
                      Bp[p] + (size_t)(n0 + r) * Kfull + k0 + ld_c);
            }
        }
    };

    float acc[4][4][4];
    #pragma unroll
    for (int i = 0; i < 4; ++i)
        #pragma unroll
        for (int j = 0; j < 4; ++j)
            #pragma unroll
            for (int q = 0; q < 4; ++q) acc[i][j][q] = 0.f;

    int nchunks = Kfull / 32;
    if (MODE == 2) {
        const int nv = (kl + 31) >> 5;
        nchunks = nv < nchunks ? nv : nchunks;
    }

    load_chunk(0, 0);
    CP_COMMIT();
    if (nchunks > 1) { load_chunk(32, 1); CP_COMMIT(); }

    const int a_row = (lane & 15);
    const int a_hi  = (lane >> 4);
    const int b_row = (lane & 7) + ((lane >> 4) << 3);
    const int b_hi  = ((lane >> 3) & 1);

    for (int t = 0; t < nchunks; ++t) {
        if (t + 1 < nchunks) CP_WAIT1(); else CP_WAIT0();
        __syncthreads();
        if (t + 2 < nchunks) {
            load_chunk((t + 2) * 32, (t + 2) % NSTAGE);
            CP_COMMIT();
        }

        const uint32_t tb  = sb + (uint32_t)(t % NSTAGE) * BUF_BYTES;
        const uint32_t Ah_ = tb;
        const uint32_t Al_ = tb + PART_BYTES;
        const uint32_t Bh_ = tb + 2 * PART_BYTES;
        const uint32_t Bl_ = tb + 3 * PART_BYTES;

        #pragma unroll
        for (int kk = 0; kk < 2; ++kk) {
            uint32_t bh[2][4], bl[2][4], a[4][4];
            uint32_t aoff[4];
            #pragma unroll
            for (int np = 0; np < 2; ++np) {
                const int row = wn * 32 + np * 16 + b_row;
                const uint32_t boff =
                    (uint32_t)(row * 64 + (((kk * 2 + b_hi) ^ ((row >> 1) & 3)) * 16));
                lm4(bh[np], Bh_ + boff);
                lm4(bl[np], Bl_ + boff);
            }
            #pragma unroll
            for (int mt = 0; mt < 4; ++mt) {
                const int row = wm * 64 + mt * 16 + a_row;
                aoff[mt] =
                    (uint32_t)(row * 64 + (((kk * 2 + a_hi) ^ ((row >> 1) & 3)) * 16));
                lm4(a[mt], Ah_ + aoff[mt]);
            }
            #pragma unroll
            for (int mt = 0; mt < 4; ++mt)
                #pragma unroll
                for (int nf = 0; nf < 4; ++nf) {
                    mma16816(acc[mt][nf], a[mt], bh[nf >> 1][(nf & 1) * 2],
                                                 bh[nf >> 1][(nf & 1) * 2 + 1]);
                    mma16816(acc[mt][nf], a[mt], bl[nf >> 1][(nf & 1) * 2],
                                                 bl[nf >> 1][(nf & 1) * 2 + 1]);
                }
            #pragma unroll
            for (int mt = 0; mt < 4; ++mt)
                lm4(a[mt], Al_ + aoff[mt]);
            #pragma unroll
            for (int mt = 0; mt < 4; ++mt)
                #pragma unroll
                for (int nf = 0; nf < 4; ++nf)
                    mma16816(acc[mt][nf], a[mt], bh[nf >> 1][(nf & 1) * 2],
                                                 bh[nf >> 1][(nf & 1) * 2 + 1]);
        }
    }

    float* Cb = C + (size_t)bz * strideC;
    #pragma unroll
    for (int mt = 0; mt < 4; ++mt) {
        #pragma unroll
        for (int nf = 0; nf < 4; ++nf) {
            const int n = n0 + wn * 32 + nf * 8 + (lane & 3) * 2;
            float2 vmn;
            if (MODE == 2) vmn = *(const float2*)(vm + n);
            #pragma unroll
            for (int h = 0; h < 2; ++h) {
                const int m = m0 + wm * 64 + mt * 16 + (lane >> 2) + h * 8;
                float2 v = make_float2(acc[mt][nf][h * 2], acc[mt][nf][h * 2 + 1]);
                if (MODE == 2 && m >= ql) v = vmn;
                *(float2*)(Cb + (size_t)m * ldc + n) = v;
            }
        }
    }
}

// ---------------------------------------------------------------------------
// Merged length-aware split for Q and K: grid.y in [0,32), sel=y>>4, b=y&15
// ---------------------------------------------------------------------------
__global__ __launch_bounds__(256)
void split2_qk(const float* __restrict__ Q, const float* __restrict__ K,
               __nv_bfloat16* __restrict__ Qh, __nv_bfloat16* __restrict__ Ql,
               __nv_bfloat16* __restrict__ Kh, __nv_bfloat16* __restrict__ Kl,
               const int* __restrict__ Qlen, const int* __restrict__ Klen)
{
    const int y   = blockIdx.y;
    const int sel = y >> 4;
    const int b   = y & 15;
    const int row = blockIdx.x;
    const float* x = sel ? K : Q;
    __nv_bfloat16* h = sel ? Kh : Qh;
    __nv_bfloat16* l = sel ? Kl : Ql;
    const int len = sel ? Klen[b] : Qlen[b];
    if (row >= ((len + 127) & ~127)) return;
    const size_t i = ((size_t)b * QT_ + row) * (D_ / 4) + threadIdx.x;
    float4 v = ((const float4*)x)[i];
    float vv[4] = {v.x, v.y, v.z, v.w};
    __nv_bfloat16 hh[4], ll[4];
    #pragma unroll
    for (int j = 0; j < 4; ++j) {
        hh[j] = __float2bfloat16_rn(vv[j]);
        ll[j] = __float2bfloat16_rn(vv[j] - __bfloat162float(hh[j]));
    }
    ((__nv_bfloat162*)h)[2 * i + 0] = __nv_bfloat162(hh[0], hh[1]);
    ((__nv_bfloat162*)h)[2 * i + 1] = __nv_bfloat162(hh[2], hh[3]);
    ((__nv_bfloat162*)l)[2 * i + 0] = __nv_bfloat162(ll[0], ll[1]);
    ((__nv_bfloat162*)l)[2 * i + 1] = __nv_bfloat162(ll[2], ll[3]);
}

// ---------------------------------------------------------------------------
// V transpose + split (k-tiles beyond ceil32(kl) skipped)
// ---------------------------------------------------------------------------
__global__ __launch_bounds__(256)
void vt_split2(const float* __restrict__ V, __nv_bfloat16* __restrict__ Th,
               __nv_bfloat16* __restrict__ Tl, const int* __restrict__ Klen)
{
    const int bz = blockIdx.z;
    const int k0 = blockIdx.y * 32;
    if (k0 >= ((Klen[bz] + 31) & ~31)) return;
    __shared__ float tile[32][33];
    const int d0 = blockIdx.x * 32;
    const int tx = threadIdx.x, ty = threadIdx.y;
    const float* src = V + (size_t)bz * KT_ * D_;
    #pragma unroll
    for (int j = 0; j < 4; ++j)
        tile[ty + 8 * j][tx] = src[(size_t)(k0 + ty + 8 * j) * D_ + d0 + tx];
    __syncthreads();
    __nv_bfloat16* th = Th + (size_t)bz * D_ * KT_;
    __nv_bfloat16* tl = Tl + (size_t)bz * D_ * KT_;
    #pragma unroll
    for (int j = 0; j < 4; ++j) {
        const int d = d0 + ty + 8 * j;
        const float f = tile[tx][ty + 8 * j];
        const __nv_bfloat16 h = __float2bfloat16_rn(f);
        const __nv_bfloat16 l = __float2bfloat16_rn(f - __bfloat162float(h));
        th[(size_t)d * KT_ + k0 + tx] = h;
        tl[(size_t)d * KT_ + k0 + tx] = l;
    }
}

// ---------------------------------------------------------------------------
// vmean two-stage (over ALL KT rows)
// ---------------------------------------------------------------------------
__global__ __launch_bounds__(128)
void vmean_part(const float* __restrict__ V, float* __restrict__ P)
{
    const int b  = blockIdx.z;
    const int ks = blockIdx.y;
    const int d  = blockIdx.x * 128 + threadIdx.x;
    const float* src = V + (size_t)b * KT_ * D_ + (size_t)ks * (KT_ / KSPLIT) * D_ + d;
    float a0 = 0.f, a1 = 0.f, a2 = 0.f, a3 = 0.f;
    #pragma unroll 4
    for (int k = 0; k < KT_ / KSPLIT; k += 4) {
        a0 += src[(size_t)(k    ) * D_];
        a1 += src[(size_t)(k + 1) * D_];
        a2 += src[(size_t)(k + 2) * D_];
        a3 += src[(size_t)(k + 3) * D_];
    }
    P[((size_t)b * KSPLIT + ks) * D_ + d] = (a0 + a1) + (a2 + a3);
}

__global__ __launch_bounds__(256)
void vmean_red(const float* __restrict__ P, float* __restrict__ M)
{
    const int idx = blockIdx.x * 256 + threadIdx.x;
    const int b = idx / D_, d = idx % D_;
    const float* p = P + (size_t)b * KSPLIT * D_ + d;
    float s = 0.f;
    #pragma unroll
    for (int i = 0; i < KSPLIT; ++i) s += p[(size_t)i * D_];
    M[idx] = s * (1.0f / KT_);
}

// ---------------------------------------------------------------------------
// Length-aware softmax + split. Launched on batch SLICES: S/Ph/Pl/Qlen/Klen
// are pre-offset to the first batch of the slice; b = row / QT_ within slice.
// ---------------------------------------------------------------------------
__global__ __launch_bounds__(256)
void softmax_split(const float* __restrict__ S, __nv_bfloat16* __restrict__ Ph,
                   __nv_bfloat16* __restrict__ Pl,
                   const int* __restrict__ Qlen, const int* __restrict__ Klen)
{
    const size_t row = blockIdx.x;
    const int b = (int)(row / QT_);
    const int q = (int)(row % QT_);
    const int ql = Qlen[b];
    const int kl = Klen[b];
    const int kend = (kl + 31) & ~31;
    const int tid = threadIdx.x, lane = tid & 31, wid = tid >> 5;
    const int base = tid * 8;

    if (q >= ((ql + 127) & ~127)) return;

    __nv_bfloat162* ph = (__nv_bfloat162*)(Ph + row * KT_);
    __nv_bfloat162* pl = (__nv_bfloat162*)(Pl + row * KT_);

    if (q >= ql) {
        if (base < kend) {
            const __nv_bfloat162 z = __float2bfloat162_rn(0.f);
            #pragma unroll
            for (int j = 0; j < 4; ++j) { ph[tid * 4 + j] = z; pl[tid * 4 + j] = z; }
        }
        return;
    }

    __shared__ float red[8];
    const float* srow = S + row * KT_;

    float x[8];
    if (base + 8 <= kl) {
        float4 a = ((const float4*)srow)[tid * 2];
        float4 c = ((const float4*)srow)[tid * 2 + 1];
        x[0] = a.x; x[1] = a.y; x[2] = a.z; x[3] = a.w;
        x[4] = c.x; x[5] = c.y; x[6] = c.z; x[7] = c.w;
    } else {
        #pragma unroll
        for (int j = 0; j < 8; ++j)
            x[j] = (base + j < kl) ? srow[base + j] : -1e30f;
    }

    float mx = fmaxf(fmaxf(fmaxf(x[0], x[1]), fmaxf(x[2], x[3])),
                     fmaxf(fmaxf(x[4], x[5]), fmaxf(x[6], x[7])));
    #pragma unroll
    for (int o = 16; o; o >>= 1) mx = fmaxf(mx, __shfl_xor_sync(~0u, mx, o));
    if (lane == 0) red[wid] = mx;
    __syncthreads();
    mx = red[0];
    #pragma unroll
    for (int i = 1; i < 8; ++i) mx = fmaxf(mx, red[i]);
    __syncthreads();

    float p[8];
    float s = 0.f;
    if (base < kl) {
        #pragma unroll
        for (int j = 0; j < 8; ++j) { p[j] = __expf(x[j] - mx); s += p[j]; }
    } else {
        #pragma unroll
        for (int j = 0; j < 8; ++j) p[j] = 0.f;
    }
    #pragma unroll
    for (int o = 16; o; o >>= 1) s += __shfl_xor_sync(~0u, s, o);
    if (lane == 0) red[wid] = s;
    __syncthreads();
    s = red[0];
    #pragma unroll
    for (int i = 1; i < 8; ++i) s += red[i];

    if (base >= kend) return;

    const float inv = 1.0f / s;
    __nv_bfloat16 hh[8], ll[8];
    #pragma unroll
    for (int j = 0; j < 8; ++j) {
        const float pv = p[j] * inv;
        hh[j] = __float2bfloat16_rn(pv);
        ll[j] = __float2bfloat16_rn(pv - __bfloat162float(hh[j]));
    }
    #pragma unroll
    for (int j = 0; j < 4; ++j) {
        ph[tid * 4 + j] = __nv_bfloat162(hh[2 * j], hh[2 * j + 1]);
        pl[tid * 4 + j] = __nv_bfloat162(ll[2 * j], ll[2 * j + 1]);
    }
}

// ---------------------------------------------------------------------------
// Launch. One side stream (R7-proven within the allocation guard):
//   main: split_qk -> GEMM1(all) -> softmax(0-7) -> softmax(8-15)
//         -> [evV] GEMM2(8-15) -> join
//   s2:   [evSplit] V-path -> [evS0] GEMM2(0-7)
// V-path hides under GEMM1; GEMM2 first half overlaps softmax second half.
// ---------------------------------------------------------------------------
extern "C" void kernel_launch(void* const* d_in, const int* in_sizes, int n_in,
                              void* d_out, int out_size)
{
    const float* Q    = (const float*)d_in[0];
    const float* K    = (const float*)d_in[1];
    const float* V    = (const float*)d_in[2];
    const int*   Qlen = (const int*)d_in[3];
    const int*   Klen = (const int*)d_in[4];
    float*       O    = (float*)d_out;

    float *S, *Vm, *Vp; __nv_bfloat16 *Qh, *Ql, *Kh, *Kl, *Ph, *Pl, *Vh, *Vl;
    cudaGetSymbolAddress((void**)&S,  g_S);
    cudaGetSymbolAddress((void**)&Vm, g_Vm);
    cudaGetSymbolAddress((void**)&Vp, g_Vp);
    cudaGetSymbolAddress((void**)&Qh, g_Qh); cudaGetSymbolAddress((void**)&Ql, g_Ql);
    cudaGetSymbolAddress((void**)&Kh, g_Kh); cudaGetSymbolAddress((void**)&Kl, g_Kl);
    cudaGetSymbolAddress((void**)&Ph, g_Ph); cudaGetSymbolAddress((void**)&Pl, g_Pl);
    cudaGetSymbolAddress((void**)&Vh, g_Vh); cudaGetSymbolAddress((void**)&Vl, g_Vl);

    static cudaStream_t s2 = nullptr;
    static cudaEvent_t evSplit = nullptr, evV = nullptr, evS0 = nullptr, evG2a = nullptr;
    if (s2 == nullptr) {
        cudaStreamCreateWithFlags(&s2, cudaStreamNonBlocking);
        cudaEventCreateWithFlags(&evSplit, cudaEventDisableTiming);
        cudaEventCreateWithFlags(&evV,     cudaEventDisableTiming);
        cudaEventCreateWithFlags(&evS0,    cudaEventDisableTiming);
        cudaEventCreateWithFlags(&evG2a,   cudaEventDisableTiming);
    }

    const int SMEM = NSTAGE * BUF_BYTES;   // 98304
    cudaFuncSetAttribute(mma_gemm<1>, cudaFuncAttributeMaxDynamicSharedMemorySize, SMEM);
    cudaFuncSetAttribute(mma_gemm<2>, cudaFuncAttributeMaxDynamicSharedMemorySize, SMEM);

    const int HB = B_ / 2;                   // 8 batches per half
    const size_t oS8  = (size_t)HB * QT_ * KT_;
    const size_t oVT8 = (size_t)HB * D_ * KT_;
    const size_t oQ8  = (size_t)HB * QT_ * D_;

    // main: split Q/K
    split2_qk<<<dim3(QT_, 32), 256>>>(Q, K, Qh, Ql, Kh, Kl, Qlen, Klen);
    cudaEventRecord(evSplit, 0);

    // s2: V-path, concurrent with GEMM1 on main
    cudaStreamWaitEvent(s2, evSplit, 0);
    vt_split2<<<dim3(D_ / 32, KT_ / 32, B_), dim3(32, 8), 0, s2>>>(V, Vh, Vl, Klen);
    vmean_part<<<dim3(D_ / 128, KSPLIT, B_), 128, 0, s2>>>(V, Vp);
    vmean_red<<<(B_ * D_) / 256, 256, 0, s2>>>(Vp, Vm);
    cudaEventRecord(evV, s2);

    // main: GEMM1 (all batches)
    mma_gemm<1><<<dim3(KT_ / 128, QT_ / 128, B_), 256, SMEM>>>(
        Qh, Ql, Kh, Kl, S, D_, KT_,
        (long)QT_ * D_, (long)KT_ * D_, (long)QT_ * KT_, Qlen, Klen, nullptr);

    // main: softmax first half, then second half
    softmax_split<<<HB * QT_, 256>>>(S, Ph, Pl, Qlen, Klen);
    cudaEventRecord(evS0, 0);
    softmax_split<<<HB * QT_, 256>>>(S + oS8, Ph + oS8, Pl + oS8, Qlen + HB, Klen + HB);

    // s2: GEMM2 first half (needs V-path done [in-stream] + softmax first half)
    cudaStreamWaitEvent(s2, evS0, 0);
    mma_gemm<2><<<dim3(D_ / 128, QT_ / 128, HB), 256, SMEM, s2>>>(
        Ph, Pl, Vh, Vl, O, KT_, D_,
        (long)QT_ * KT_, (long)D_ * KT_, (long)QT_ * D_, Qlen, Klen, Vm);
    cudaEventRecord(evG2a, s2);

    // main: GEMM2 second half (needs V-path done)
    cudaStreamWaitEvent(0, evV, 0);
    mma_gemm<2><<<dim3(D_ / 128, QT_ / 128, HB), 256, SMEM>>>(
        Ph + oS8, Pl + oS8, Vh + oVT8, Vl + oVT8, O + oQ8, KT_, D_,
        (long)QT_ * KT_, (long)D_ * KT_, (long)QT_ * D_,
        Qlen + HB, Klen + HB, Vm + (size_t)HB * D_);

    // join
    cudaStreamWaitEvent(0, evG2a, 0);
}